// round 3
// baseline (speedup 1.0000x reference)
#include <cuda_runtime.h>

#define Bb   8
#define Nn   2048
#define Cc   64
#define MIDm 256
#define KK   16
#define R2c  0.0225f
#define EPSc 1e-5f

// packed fp32 FMA: d = a*b + d (2 lanes per instruction, Blackwell f32x2 path)
#define FFMA2(acc, a, b) asm("fma.rn.f32x2 %0, %1, %2, %0;" : "+l"(acc) : "l"(a), "l"(b))

__device__ __forceinline__ float f2lo(unsigned long long v) {
    return __uint_as_float((unsigned)v);
}
__device__ __forceinline__ float f2hi(unsigned long long v) {
    return __uint_as_float((unsigned)(v >> 32));
}

// ---------------- scratch (device globals, no allocation) ----------------
__device__ __align__(16) int    g_idx[Bb*Nn*KK];      // [b][n][16]
__device__ __align__(16) float  g_feat[Bb*Nn*Cc];     // [b][n][c]  = w1[:,3:]@f
__device__ __align__(16) float  g_m[Bb*Cc*Nn];        // [b][c][n]  = max_k x
__device__ __align__(16) float  g_y[Bb*MIDm*Nn];      // [b][c][n]
__device__ __align__(16) float  g_z[Bb*Cc*Nn];        // [b][c][n]
__device__ __align__(16) float  g_w2t[Cc*MIDm];       // [k][o] = w2[o][k]
__device__ __align__(16) float  g_w3t[MIDm*Cc];       // [k][c] = w3[c][k]
__device__ double g_s1[Cc],   g_ss1[Cc];
__device__ double g_s2[MIDm], g_ss2[MIDm];
__device__ double g_s3[Cc],   g_ss3[Cc];

// ---------------- K_gfeat: g[b][n][c] = sum_cp w1[c][3+cp] * f[b][cp][n] ----------------
// Blocks < 64 additionally perform the prep work (weight transposes + stat zeroing).
__global__ void __launch_bounds__(256) k_gfeat(const float* __restrict__ f,
                                               const float* __restrict__ w1,
                                               const float* __restrict__ w2,
                                               const float* __restrict__ w3) {
    __shared__ __align__(16) float w1t[64*68];   // [cp][c], padded
    __shared__ __align__(16) float fs[64*32];    // [cp][nl]
    __shared__ __align__(16) float gs[32*68];    // [nl][c], padded
    int tid = threadIdx.x;
    int b  = blockIdx.x >> 6;
    int n0 = (blockIdx.x & 63) << 5;

    // fused prep: 64 blocks cover 16384 elements
    if (blockIdx.x < 64) {
        int i = blockIdx.x * 256 + tid;
        if (i < Cc*MIDm) {
            int o = i >> 6, k = i & 63;           // w2: (256,64) row-major
            g_w2t[k*MIDm + o] = w2[i];
            int c = i >> 8, kk = i & 255;         // w3: (64,256) row-major
            g_w3t[kk*Cc + c] = w3[i];
        }
        if (i < Cc)   { g_s1[i]=0.0; g_ss1[i]=0.0; g_s3[i]=0.0; g_ss3[i]=0.0; }
        if (i < MIDm) { g_s2[i]=0.0; g_ss2[i]=0.0; }
    }

    for (int i = tid; i < 64*64; i += 256) {
        int c = i >> 6, cp = i & 63;
        w1t[cp*68 + c] = w1[c*67 + 3 + cp];
    }
    for (int i = tid; i < 64*32; i += 256) {
        int cp = i >> 5, nl = i & 31;
        fs[i] = f[(b*64 + cp)*2048 + n0 + nl];
    }
    __syncthreads();

    int nl = tid & 31, cg = tid >> 5;    // channels cg*8 .. cg*8+7
    float acc[8];
    #pragma unroll
    for (int i = 0; i < 8; i++) acc[i] = 0.f;

    #pragma unroll 8
    for (int cp = 0; cp < 64; cp++) {
        float fv = fs[cp*32 + nl];
        float4 wa = *(const float4*)&w1t[cp*68 + cg*8];
        float4 wb = *(const float4*)&w1t[cp*68 + cg*8 + 4];
        acc[0] = fmaf(wa.x, fv, acc[0]);
        acc[1] = fmaf(wa.y, fv, acc[1]);
        acc[2] = fmaf(wa.z, fv, acc[2]);
        acc[3] = fmaf(wa.w, fv, acc[3]);
        acc[4] = fmaf(wb.x, fv, acc[4]);
        acc[5] = fmaf(wb.y, fv, acc[5]);
        acc[6] = fmaf(wb.z, fv, acc[6]);
        acc[7] = fmaf(wb.w, fv, acc[7]);
    }
    #pragma unroll
    for (int i = 0; i < 8; i++) gs[nl*68 + cg*8 + i] = acc[i];
    __syncthreads();
    for (int i = tid; i < 2048; i += 256) {
        int nn = i >> 6, c = i & 63;
        g_feat[(b*2048 + n0 + nn)*64 + c] = gs[nn*68 + c];
    }
}

// ---------------- K_ballq: warp-per-point ascending scan, early exit ----------------
__global__ void __launch_bounds__(512) k_ballq(const float* __restrict__ p) {
    __shared__ float px[2048], py[2048], pz[2048];
    __shared__ int   ob[16][16];
    int tid = threadIdx.x;
    int b  = blockIdx.x >> 7;             // 128 blocks per batch
    int n0 = (blockIdx.x & 127) << 4;     // 16 points per block

    for (int i = tid; i < 2048; i += 512) {
        const float* pp = p + (size_t)(b*2048 + i)*3;
        px[i] = pp[0]; py[i] = pp[1]; pz[i] = pp[2];
    }
    __syncthreads();

    int w = tid >> 5, lane = tid & 31;
    int n = n0 + w;
    float qx = px[n], qy = py[n], qz = pz[n];
    int cnt = 0;
    for (int j0 = 0; j0 < 2048; j0 += 32) {
        int j = j0 + lane;
        float dx = __fsub_rn(px[j], qx);
        float dy = __fsub_rn(py[j], qy);
        float dz = __fsub_rn(pz[j], qz);
        float d2 = __fadd_rn(__fadd_rn(__fmul_rn(dx,dx), __fmul_rn(dy,dy)), __fmul_rn(dz,dz));
        bool q = d2 < R2c;
        unsigned mask = __ballot_sync(0xffffffffu, q);
        if (mask) {
            int r = cnt + __popc(mask & ((1u << lane) - 1u));
            if (q && r < 16) ob[w][r] = j;
            cnt += __popc(mask);
            if (cnt >= 16) break;
        }
    }
    __syncwarp();
    if (cnt < 16) {                       // pad with first neighbor (self always qualifies)
        int first = ob[w][0];
        if (lane >= cnt && lane < 16) ob[w][lane] = first;
        __syncwarp();
    }
    if (lane < 16) g_idx[(b*2048 + n)*16 + lane] = ob[w][lane];
}

// ---------------- K_agg: x = g[j] + w1p@dp ; stats1 + max over K ----------------
__global__ void __launch_bounds__(256) k_agg(const float* __restrict__ p,
                                             const float* __restrict__ w1) {
    __shared__ float ms[64*8];
    __shared__ float s1s[64], q1s[64];
    int tid = threadIdx.x;
    if (tid < 64) { s1s[tid] = 0.f; q1s[tid] = 0.f; }
    __syncthreads();

    int b  = blockIdx.x >> 8;
    int n0 = (blockIdx.x & 255) << 3;   // 8 points per block (1 per warp)
    int w = tid >> 5, lane = tid & 31;
    int n = n0 + w;
    int c0 = lane * 2;

    float wx0 = w1[c0*67+0],     wy0 = w1[c0*67+1],     wz0 = w1[c0*67+2];
    float wx1 = w1[(c0+1)*67+0], wy1 = w1[(c0+1)*67+1], wz1 = w1[(c0+1)*67+2];
    const float* pc = p + (size_t)(b*2048 + n)*3;
    float cx = pc[0], cy = pc[1], cz = pc[2];
    int jr = g_idx[(b*2048 + n)*16 + (lane & 15)];

    // lanes 0-15 fetch their neighbor's coords in parallel
    float dxr = 0.f, dyr = 0.f, dzr = 0.f;
    if (lane < 16) {
        const float* pj = p + (size_t)(b*2048 + jr)*3;
        dxr = pj[0] - cx; dyr = pj[1] - cy; dzr = pj[2] - cz;
    }

    int js[16];
    #pragma unroll
    for (int k = 0; k < 16; k++) js[k] = __shfl_sync(0xffffffffu, jr, k);

    // batched gather: 16 independent float2 loads in flight
    float2 gv[16];
    #pragma unroll
    for (int k = 0; k < 16; k++)
        gv[k] = __ldg((const float2*)(g_feat + (size_t)(b*2048 + js[k])*64 + c0));

    float mx0 = -3.402823466e38f, mx1 = -3.402823466e38f;
    float s0 = 0.f, q0 = 0.f, s1v = 0.f, q1v = 0.f;
    #pragma unroll
    for (int k = 0; k < 16; k++) {
        float dx = __shfl_sync(0xffffffffu, dxr, k);
        float dy = __shfl_sync(0xffffffffu, dyr, k);
        float dz = __shfl_sync(0xffffffffu, dzr, k);
        float v0 = fmaf(wx0, dx, fmaf(wy0, dy, fmaf(wz0, dz, gv[k].x)));
        float v1 = fmaf(wx1, dx, fmaf(wy1, dy, fmaf(wz1, dz, gv[k].y)));
        mx0 = fmaxf(mx0, v0); mx1 = fmaxf(mx1, v1);
        s0 += v0;  q0  = fmaf(v0, v0, q0);
        s1v += v1; q1v = fmaf(v1, v1, q1v);
    }
    ms[c0*8 + w]     = mx0;
    ms[(c0+1)*8 + w] = mx1;
    atomicAdd(&s1s[c0],   s0);  atomicAdd(&q1s[c0],   q0);
    atomicAdd(&s1s[c0+1], s1v); atomicAdd(&q1s[c0+1], q1v);
    __syncthreads();
    for (int i = tid; i < 512; i += 256) {
        int c = i >> 3, nl = i & 7;
        g_m[(b*64 + c)*2048 + n0 + nl] = ms[i];
    }
    if (tid < 64) {
        atomicAdd(&g_s1[tid],  (double)s1s[tid]);
        atomicAdd(&g_ss1[tid], (double)q1s[tid]);
    }
}

// ---------------- K_mlp1: y = w2 @ relu(bn1(m)) ; stats2 (packed f32x2) ----------------
// Thread: 8 n x 8 c (c as 4 true pairs from w2t; h duplicated in shared).
__global__ void __launch_bounds__(256, 2) k_mlp1(const float* __restrict__ g1,
                                                 const float* __restrict__ b1) {
    __shared__ __align__(16) float hs[64*128];   // [k][2n] duplicated, 32 KB
    __shared__ float sc[64], sh[64];
    __shared__ float s2s[MIDm], q2s[MIDm];
    int tid = threadIdx.x;
    if (tid < 64) {
        double cnt = (double)(Bb*Nn*KK);
        double mu  = g_s1[tid] / cnt;
        double var = g_ss1[tid] / cnt - mu*mu;
        float s = g1[tid] * rsqrtf((float)var + EPSc);
        sc[tid] = s;
        sh[tid] = b1[tid] - (float)mu * s;
    }
    if (tid < 256) { s2s[tid] = 0.f; q2s[tid] = 0.f; }
    __syncthreads();

    int b  = blockIdx.x >> 5;
    int n0 = (blockIdx.x & 31) << 6;
    for (int i = tid; i < 4096; i += 256) {
        int c = i >> 6, nl = i & 63;
        float v = g_m[(b*64 + c)*2048 + n0 + nl];
        v = fmaxf(0.f, fmaf(v, sc[c], sh[c]));
        *(float2*)&hs[c*128 + 2*nl] = make_float2(v, v);
    }
    __syncthreads();

    int nc = tid & 7, cc = tid >> 3;    // n: nc*8..+7 ; c: cc*8..+7 (4 pairs)
    unsigned long long acc[4][8];
    #pragma unroll
    for (int i = 0; i < 4; i++)
        #pragma unroll
        for (int j = 0; j < 8; j++) acc[i][j] = 0ull;

    #pragma unroll 4
    for (int k = 0; k < 64; k++) {
        const ulonglong2* wp = (const ulonglong2*)&g_w2t[k*256 + cc*8];
        ulonglong2 wA = __ldg(wp);
        ulonglong2 wB = __ldg(wp + 1);
        const ulonglong2* hp = (const ulonglong2*)&hs[k*128 + nc*16];
        ulonglong2 h0 = hp[0], h1 = hp[1], h2 = hp[2], h3 = hp[3];
        unsigned long long wv[4] = {wA.x, wA.y, wB.x, wB.y};
        unsigned long long hd[8] = {h0.x, h0.y, h1.x, h1.y, h2.x, h2.y, h3.x, h3.y};
        #pragma unroll
        for (int ci = 0; ci < 4; ci++)
            #pragma unroll
            for (int nj = 0; nj < 8; nj++)
                FFMA2(acc[ci][nj], wv[ci], hd[nj]);
    }
    #pragma unroll
    for (int ci = 0; ci < 4; ci++) {
        int c = cc*8 + 2*ci;            // even channel; odd = c+1
        float lo[8], hi[8];
        float sl = 0.f, ql = 0.f, sv = 0.f, qv = 0.f;
        #pragma unroll
        for (int nj = 0; nj < 8; nj++) {
            lo[nj] = f2lo(acc[ci][nj]); hi[nj] = f2hi(acc[ci][nj]);
            sl += lo[nj]; ql = fmaf(lo[nj], lo[nj], ql);
            sv += hi[nj]; qv = fmaf(hi[nj], hi[nj], qv);
        }
        atomicAdd(&s2s[c],   sl); atomicAdd(&q2s[c],   ql);
        atomicAdd(&s2s[c+1], sv); atomicAdd(&q2s[c+1], qv);
        float* yp0 = &g_y[(size_t)(b*256 + c)*2048 + n0 + nc*8];
        float* yp1 = yp0 + 2048;
        *(float4*)yp0       = make_float4(lo[0], lo[1], lo[2], lo[3]);
        *(float4*)(yp0 + 4) = make_float4(lo[4], lo[5], lo[6], lo[7]);
        *(float4*)yp1       = make_float4(hi[0], hi[1], hi[2], hi[3]);
        *(float4*)(yp1 + 4) = make_float4(hi[4], hi[5], hi[6], hi[7]);
    }
    __syncthreads();
    if (tid < 256) {
        atomicAdd(&g_s2[tid],  (double)s2s[tid]);
        atomicAdd(&g_ss2[tid], (double)q2s[tid]);
    }
}

// ---------------- K_mlp2: z = w3 @ relu(bn2(y)) ; stats3 (packed f32x2) ----------------
// Thread: 8 n x 4 c (c as 2 true pairs from w3t; h duplicated in shared, k-chunked 32).
__global__ void __launch_bounds__(256, 2) k_mlp2(const float* __restrict__ g2,
                                                 const float* __restrict__ b2) {
    __shared__ __align__(16) float hs[32*256];   // [kk][2n] duplicated, 32 KB
    __shared__ float sc[256], sh[256];
    __shared__ float s3s[64], q3s[64];
    int tid = threadIdx.x;
    if (tid < 256) {
        double cnt = (double)(Bb*Nn);
        double mu  = g_s2[tid] / cnt;
        double var = g_ss2[tid] / cnt - mu*mu;
        float s = g2[tid] * rsqrtf((float)var + EPSc);
        sc[tid] = s;
        sh[tid] = b2[tid] - (float)mu * s;
    }
    if (tid < 64) { s3s[tid] = 0.f; q3s[tid] = 0.f; }
    __syncthreads();

    int b  = blockIdx.x >> 4;
    int n0 = (blockIdx.x & 15) << 7;    // 128 n per block
    int nc = tid & 15, cc = tid >> 4;   // n: nc*8..+7 ; c: cc*4..+3 (2 pairs)
    unsigned long long acc[2][8];
    #pragma unroll
    for (int i = 0; i < 2; i++)
        #pragma unroll
        for (int j = 0; j < 8; j++) acc[i][j] = 0ull;

    for (int k0 = 0; k0 < 256; k0 += 32) {
        for (int i = tid; i < 4096; i += 256) {
            int kk = i >> 7, nl = i & 127;
            int c = k0 + kk;
            float v = g_y[(size_t)(b*256 + c)*2048 + n0 + nl];
            v = fmaxf(0.f, fmaf(v, sc[c], sh[c]));
            *(float2*)&hs[kk*256 + 2*nl] = make_float2(v, v);
        }
        __syncthreads();
        #pragma unroll 4
        for (int kk = 0; kk < 32; kk++) {
            ulonglong2 w = __ldg((const ulonglong2*)&g_w3t[(k0+kk)*64 + cc*4]);
            const ulonglong2* hp = (const ulonglong2*)&hs[kk*256 + nc*16];
            ulonglong2 h0 = hp[0], h1 = hp[1], h2 = hp[2], h3 = hp[3];
            unsigned long long hd[8] = {h0.x, h0.y, h1.x, h1.y, h2.x, h2.y, h3.x, h3.y};
            #pragma unroll
            for (int nj = 0; nj < 8; nj++) FFMA2(acc[0][nj], w.x, hd[nj]);
            #pragma unroll
            for (int nj = 0; nj < 8; nj++) FFMA2(acc[1][nj], w.y, hd[nj]);
        }
        __syncthreads();
    }
    #pragma unroll
    for (int ci = 0; ci < 2; ci++) {
        int c = cc*4 + 2*ci;            // even channel; odd = c+1
        float lo[8], hi[8];
        float sl = 0.f, ql = 0.f, sv = 0.f, qv = 0.f;
        #pragma unroll
        for (int nj = 0; nj < 8; nj++) {
            lo[nj] = f2lo(acc[ci][nj]); hi[nj] = f2hi(acc[ci][nj]);
            sl += lo[nj]; ql = fmaf(lo[nj], lo[nj], ql);
            sv += hi[nj]; qv = fmaf(hi[nj], hi[nj], qv);
        }
        atomicAdd(&s3s[c],   sl); atomicAdd(&q3s[c],   ql);
        atomicAdd(&s3s[c+1], sv); atomicAdd(&q3s[c+1], qv);
        float* zp0 = &g_z[(size_t)(b*64 + c)*2048 + n0 + nc*8];
        float* zp1 = zp0 + 2048;
        *(float4*)zp0       = make_float4(lo[0], lo[1], lo[2], lo[3]);
        *(float4*)(zp0 + 4) = make_float4(lo[4], lo[5], lo[6], lo[7]);
        *(float4*)zp1       = make_float4(hi[0], hi[1], hi[2], hi[3]);
        *(float4*)(zp1 + 4) = make_float4(hi[4], hi[5], hi[6], hi[7]);
    }
    __syncthreads();
    if (tid < 64) {
        atomicAdd(&g_s3[tid],  (double)s3s[tid]);
        atomicAdd(&g_ss3[tid], (double)q3s[tid]);
    }
}

// ---------------- K_out: relu(bn3(z) + f) ----------------
__global__ void __launch_bounds__(256) k_out(const float* __restrict__ f,
                                             const float* __restrict__ g3,
                                             const float* __restrict__ b3,
                                             float* __restrict__ out) {
    __shared__ float sc[64], sh[64];
    int tid = threadIdx.x;
    if (tid < 64) {
        double cnt = (double)(Bb*Nn);
        double mu  = g_s3[tid] / cnt;
        double var = g_ss3[tid] / cnt - mu*mu;
        float s = g3[tid] * rsqrtf((float)var + EPSc);
        sc[tid] = s;
        sh[tid] = b3[tid] - (float)mu * s;
    }
    __syncthreads();
    int i = blockIdx.x * 256 + tid;     // float4 index
    int base = i * 4;
    int c = (base >> 11) & 63;
    float4 z  = *(const float4*)&g_z[base];
    float4 fv = *(const float4*)&f[base];
    float4 o;
    o.x = fmaxf(0.f, fmaf(z.x, sc[c], sh[c]) + fv.x);
    o.y = fmaxf(0.f, fmaf(z.y, sc[c], sh[c]) + fv.y);
    o.z = fmaxf(0.f, fmaf(z.z, sc[c], sh[c]) + fv.z);
    o.w = fmaxf(0.f, fmaf(z.w, sc[c], sh[c]) + fv.w);
    *(float4*)&out[base] = o;
}

// ---------------- launch ----------------
extern "C" void kernel_launch(void* const* d_in, const int* in_sizes, int n_in,
                              void* d_out, int out_size) {
    const float* p  = (const float*)d_in[0];
    const float* f  = (const float*)d_in[1];
    const float* w1 = (const float*)d_in[2];
    const float* g1 = (const float*)d_in[3];
    const float* b1 = (const float*)d_in[4];
    const float* w2 = (const float*)d_in[5];
    const float* g2 = (const float*)d_in[6];
    const float* b2 = (const float*)d_in[7];
    const float* w3 = (const float*)d_in[8];
    const float* g3 = (const float*)d_in[9];
    const float* b3 = (const float*)d_in[10];
    float* out = (float*)d_out;

    k_gfeat<<<512,  256>>>(f, w1, w2, w3);
    k_ballq<<<1024, 512>>>(p);
    k_agg  <<<2048, 256>>>(p, w1);
    k_mlp1 <<<256,  256>>>(g1, b1);
    k_mlp2 <<<128,  256>>>(g2, b2);
    k_out  <<<1024, 256>>>(f, g3, b3, out);
}

// round 4
// speedup vs baseline: 1.3850x; 1.3850x over previous
#include <cuda_runtime.h>

#define Bb   8
#define Nn   2048
#define Cc   64
#define MIDm 256
#define KK   16
#define R2c  0.0225f
#define EPSc 1e-5f

// packed fp32 FMA: d = a*b + d (2 lanes per instruction, Blackwell f32x2 path)
#define FFMA2(acc, a, b) asm("fma.rn.f32x2 %0, %1, %2, %0;" : "+l"(acc) : "l"(a), "l"(b))

__device__ __forceinline__ float f2lo(unsigned long long v) {
    return __uint_as_float((unsigned)v);
}
__device__ __forceinline__ float f2hi(unsigned long long v) {
    return __uint_as_float((unsigned)(v >> 32));
}

// ---------------- scratch (device globals, no allocation) ----------------
__device__ __align__(16) int    g_idx[Bb*Nn*KK];      // [b][n][16]
__device__ __align__(16) float  g_feat[Bb*Nn*Cc];     // [b][n][c]  = w1[:,3:]@f
__device__ __align__(16) float  g_m[Bb*Cc*Nn];        // [b][c][n]  = max_k x
__device__ __align__(16) float  g_y[Bb*MIDm*Nn];      // [b][c][n]
__device__ __align__(16) float  g_z[Bb*Cc*Nn];        // [b][c][n]
__device__ __align__(16) float  g_w2d[Cc*MIDm*2];     // [k][2o]: w2[o][k] duplicated pairs
__device__ __align__(16) float  g_w3d[MIDm*Cc*2];     // [k][2c]: w3[c][k] duplicated pairs
__device__ double g_s1[Cc],   g_ss1[Cc];
__device__ double g_s2[MIDm], g_ss2[MIDm];
__device__ double g_s3[Cc],   g_ss3[Cc];

// ---------------- K_gfeat: g[b][n][c] = sum_cp w1[c][3+cp] * f[b][cp][n] ----------------
// Blocks < 64 additionally perform the prep work (dup weight transposes + stat zeroing).
__global__ void __launch_bounds__(256) k_gfeat(const float* __restrict__ f,
                                               const float* __restrict__ w1,
                                               const float* __restrict__ w2,
                                               const float* __restrict__ w3) {
    __shared__ __align__(16) float w1t[64*68];   // [cp][c], padded
    __shared__ __align__(16) float fs[64*32];    // [cp][nl]
    __shared__ __align__(16) float gs[32*68];    // [nl][c], padded
    int tid = threadIdx.x;
    int b  = blockIdx.x >> 6;
    int n0 = (blockIdx.x & 63) << 5;

    // fused prep: 64 blocks cover 16384 elements
    if (blockIdx.x < 64) {
        int i = blockIdx.x * 256 + tid;
        if (i < Cc*MIDm) {
            int o = i >> 6, k = i & 63;           // w2: (256,64) row-major
            float v2 = w2[i];
            g_w2d[k*512 + 2*o]     = v2;
            g_w2d[k*512 + 2*o + 1] = v2;
            int c = i >> 8, kk = i & 255;         // w3: (64,256) row-major
            float v3 = w3[i];
            g_w3d[kk*128 + 2*c]     = v3;
            g_w3d[kk*128 + 2*c + 1] = v3;
        }
        if (i < Cc)   { g_s1[i]=0.0; g_ss1[i]=0.0; g_s3[i]=0.0; g_ss3[i]=0.0; }
        if (i < MIDm) { g_s2[i]=0.0; g_ss2[i]=0.0; }
    }

    for (int i = tid; i < 64*64; i += 256) {
        int c = i >> 6, cp = i & 63;
        w1t[cp*68 + c] = w1[c*67 + 3 + cp];
    }
    for (int i = tid; i < 64*32; i += 256) {
        int cp = i >> 5, nl = i & 31;
        fs[i] = f[(b*64 + cp)*2048 + n0 + nl];
    }
    __syncthreads();

    int nl = tid & 31, cg = tid >> 5;    // channels cg*8 .. cg*8+7
    float acc[8];
    #pragma unroll
    for (int i = 0; i < 8; i++) acc[i] = 0.f;

    #pragma unroll 8
    for (int cp = 0; cp < 64; cp++) {
        float fv = fs[cp*32 + nl];
        float4 wa = *(const float4*)&w1t[cp*68 + cg*8];
        float4 wb = *(const float4*)&w1t[cp*68 + cg*8 + 4];
        acc[0] = fmaf(wa.x, fv, acc[0]);
        acc[1] = fmaf(wa.y, fv, acc[1]);
        acc[2] = fmaf(wa.z, fv, acc[2]);
        acc[3] = fmaf(wa.w, fv, acc[3]);
        acc[4] = fmaf(wb.x, fv, acc[4]);
        acc[5] = fmaf(wb.y, fv, acc[5]);
        acc[6] = fmaf(wb.z, fv, acc[6]);
        acc[7] = fmaf(wb.w, fv, acc[7]);
    }
    #pragma unroll
    for (int i = 0; i < 8; i++) gs[nl*68 + cg*8 + i] = acc[i];
    __syncthreads();
    for (int i = tid; i < 2048; i += 256) {
        int nn = i >> 6, c = i & 63;
        g_feat[(b*2048 + n0 + nn)*64 + c] = gs[nn*68 + c];
    }
}

// ---------------- K_ballq: warp-per-point ascending scan, early exit ----------------
__global__ void __launch_bounds__(512) k_ballq(const float* __restrict__ p) {
    __shared__ float px[2048], py[2048], pz[2048];
    __shared__ int   ob[16][16];
    int tid = threadIdx.x;
    int b  = blockIdx.x >> 7;             // 128 blocks per batch
    int n0 = (blockIdx.x & 127) << 4;     // 16 points per block

    for (int i = tid; i < 2048; i += 512) {
        const float* pp = p + (size_t)(b*2048 + i)*3;
        px[i] = pp[0]; py[i] = pp[1]; pz[i] = pp[2];
    }
    __syncthreads();

    int w = tid >> 5, lane = tid & 31;
    int n = n0 + w;
    float qx = px[n], qy = py[n], qz = pz[n];
    int cnt = 0;
    for (int j0 = 0; j0 < 2048; j0 += 32) {
        int j = j0 + lane;
        float dx = __fsub_rn(px[j], qx);
        float dy = __fsub_rn(py[j], qy);
        float dz = __fsub_rn(pz[j], qz);
        float d2 = __fadd_rn(__fadd_rn(__fmul_rn(dx,dx), __fmul_rn(dy,dy)), __fmul_rn(dz,dz));
        bool q = d2 < R2c;
        unsigned mask = __ballot_sync(0xffffffffu, q);
        if (mask) {
            int r = cnt + __popc(mask & ((1u << lane) - 1u));
            if (q && r < 16) ob[w][r] = j;
            cnt += __popc(mask);
            if (cnt >= 16) break;
        }
    }
    __syncwarp();
    if (cnt < 16) {                       // pad with first neighbor (self always qualifies)
        int first = ob[w][0];
        if (lane >= cnt && lane < 16) ob[w][lane] = first;
        __syncwarp();
    }
    if (lane < 16) g_idx[(b*2048 + n)*16 + lane] = ob[w][lane];
}

// ---------------- K_agg: x = g[j] + w1p@dp ; stats1 + max over K ----------------
__global__ void __launch_bounds__(256) k_agg(const float* __restrict__ p,
                                             const float* __restrict__ w1) {
    __shared__ float ms[64*8];
    __shared__ float s1s[64], q1s[64];
    int tid = threadIdx.x;
    if (tid < 64) { s1s[tid] = 0.f; q1s[tid] = 0.f; }
    __syncthreads();

    int b  = blockIdx.x >> 8;
    int n0 = (blockIdx.x & 255) << 3;   // 8 points per block (1 per warp)
    int w = tid >> 5, lane = tid & 31;
    int n = n0 + w;
    int c0 = lane * 2;

    float wx0 = w1[c0*67+0],     wy0 = w1[c0*67+1],     wz0 = w1[c0*67+2];
    float wx1 = w1[(c0+1)*67+0], wy1 = w1[(c0+1)*67+1], wz1 = w1[(c0+1)*67+2];
    const float* pc = p + (size_t)(b*2048 + n)*3;
    float cx = pc[0], cy = pc[1], cz = pc[2];
    int jr = g_idx[(b*2048 + n)*16 + (lane & 15)];

    // lanes 0-15 fetch their neighbor's coords in parallel
    float dxr = 0.f, dyr = 0.f, dzr = 0.f;
    if (lane < 16) {
        const float* pj = p + (size_t)(b*2048 + jr)*3;
        dxr = pj[0] - cx; dyr = pj[1] - cy; dzr = pj[2] - cz;
    }

    int js[16];
    #pragma unroll
    for (int k = 0; k < 16; k++) js[k] = __shfl_sync(0xffffffffu, jr, k);

    // batched gather: 16 independent float2 loads in flight
    float2 gv[16];
    #pragma unroll
    for (int k = 0; k < 16; k++)
        gv[k] = __ldg((const float2*)(g_feat + (size_t)(b*2048 + js[k])*64 + c0));

    float mx0 = -3.402823466e38f, mx1 = -3.402823466e38f;
    float s0 = 0.f, q0 = 0.f, s1v = 0.f, q1v = 0.f;
    #pragma unroll
    for (int k = 0; k < 16; k++) {
        float dx = __shfl_sync(0xffffffffu, dxr, k);
        float dy = __shfl_sync(0xffffffffu, dyr, k);
        float dz = __shfl_sync(0xffffffffu, dzr, k);
        float v0 = fmaf(wx0, dx, fmaf(wy0, dy, fmaf(wz0, dz, gv[k].x)));
        float v1 = fmaf(wx1, dx, fmaf(wy1, dy, fmaf(wz1, dz, gv[k].y)));
        mx0 = fmaxf(mx0, v0); mx1 = fmaxf(mx1, v1);
        s0 += v0;  q0  = fmaf(v0, v0, q0);
        s1v += v1; q1v = fmaf(v1, v1, q1v);
    }
    ms[c0*8 + w]     = mx0;
    ms[(c0+1)*8 + w] = mx1;
    atomicAdd(&s1s[c0],   s0);  atomicAdd(&q1s[c0],   q0);
    atomicAdd(&s1s[c0+1], s1v); atomicAdd(&q1s[c0+1], q1v);
    __syncthreads();
    for (int i = tid; i < 512; i += 256) {
        int c = i >> 3, nl = i & 7;
        g_m[(b*64 + c)*2048 + n0 + nl] = ms[i];
    }
    if (tid < 64) {
        atomicAdd(&g_s1[tid],  (double)s1s[tid]);
        atomicAdd(&g_ss1[tid], (double)q1s[tid]);
    }
}

// ---------------- K_mlp1: y = w2 @ relu(bn1(m)) ; stats2 ----------------
// f32x2 paired over n: hs natural layout (no extra LDS bytes); weights duplicated
// in g_w2d so each FFMA2 does 2 n-values of the same channel.
// Thread tile: 8 c x 8 n (4 n-pairs). Block: 256 c x 64 n.
__global__ void __launch_bounds__(256, 2) k_mlp1(const float* __restrict__ g1,
                                                 const float* __restrict__ b1) {
    __shared__ __align__(16) float hs[64*64];    // [k][nl], 16 KB
    __shared__ float sc[64], sh[64];
    __shared__ float s2s[MIDm], q2s[MIDm];
    int tid = threadIdx.x;
    if (tid < 64) {
        double cnt = (double)(Bb*Nn*KK);
        double mu  = g_s1[tid] / cnt;
        double var = g_ss1[tid] / cnt - mu*mu;
        float s = g1[tid] * rsqrtf((float)var + EPSc);
        sc[tid] = s;
        sh[tid] = b1[tid] - (float)mu * s;
    }
    if (tid < 256) { s2s[tid] = 0.f; q2s[tid] = 0.f; }
    __syncthreads();

    int b  = blockIdx.x >> 5;
    int n0 = (blockIdx.x & 31) << 6;
    for (int i = tid; i < 4096; i += 256) {
        int c = i >> 6, nl = i & 63;
        float v = g_m[(b*64 + c)*2048 + n0 + nl];
        hs[i] = fmaxf(0.f, fmaf(v, sc[c], sh[c]));
    }
    __syncthreads();

    int nc = tid & 7, cc = tid >> 3;    // n: nc*8..+7 ; c: cc*8..+7
    unsigned long long acc[8][4];
    #pragma unroll
    for (int i = 0; i < 8; i++)
        #pragma unroll
        for (int j = 0; j < 4; j++) acc[i][j] = 0ull;

    #pragma unroll 2
    for (int k = 0; k < 64; k++) {
        const float* wb = &g_w2d[k*512 + cc*16];
        ulonglong2 wA = __ldg((const ulonglong2*)wb);
        ulonglong2 wB = __ldg((const ulonglong2*)(wb + 4));
        ulonglong2 wC = __ldg((const ulonglong2*)(wb + 8));
        ulonglong2 wD = __ldg((const ulonglong2*)(wb + 12));
        const ulonglong2* hp = (const ulonglong2*)&hs[k*64 + nc*8];
        ulonglong2 h0 = hp[0], h1 = hp[1];
        unsigned long long wv[8] = {wA.x, wA.y, wB.x, wB.y, wC.x, wC.y, wD.x, wD.y};
        unsigned long long hd[4] = {h0.x, h0.y, h1.x, h1.y};
        #pragma unroll
        for (int ci = 0; ci < 8; ci++)
            #pragma unroll
            for (int np = 0; np < 4; np++)
                FFMA2(acc[ci][np], wv[ci], hd[np]);
    }
    #pragma unroll
    for (int ci = 0; ci < 8; ci++) {
        int c = cc*8 + ci;
        float v0 = f2lo(acc[ci][0]), v1 = f2hi(acc[ci][0]);
        float v2 = f2lo(acc[ci][1]), v3 = f2hi(acc[ci][1]);
        float v4 = f2lo(acc[ci][2]), v5 = f2hi(acc[ci][2]);
        float v6 = f2lo(acc[ci][3]), v7 = f2hi(acc[ci][3]);
        float s = ((v0+v1)+(v2+v3)) + ((v4+v5)+(v6+v7));
        float q = fmaf(v0,v0, fmaf(v1,v1, fmaf(v2,v2, fmaf(v3,v3,
                  fmaf(v4,v4, fmaf(v5,v5, fmaf(v6,v6, v7*v7)))))));
        atomicAdd(&s2s[c], s); atomicAdd(&q2s[c], q);
        float* yp = &g_y[(size_t)(b*256 + c)*2048 + n0 + nc*8];
        *(float4*)yp       = make_float4(v0, v1, v2, v3);
        *(float4*)(yp + 4) = make_float4(v4, v5, v6, v7);
    }
    __syncthreads();
    if (tid < 256) {
        atomicAdd(&g_s2[tid],  (double)s2s[tid]);
        atomicAdd(&g_ss2[tid], (double)q2s[tid]);
    }
}

// ---------------- K_mlp2: z = w3 @ relu(bn2(y)) ; stats3 ----------------
// f32x2 paired over n, dup weights. Thread tile: 2 c x 8 n. Block: 64 c x 64 n.
// Grid 256 blocks (>=1/SM), 3 blocks/SM.
__global__ void __launch_bounds__(256, 3) k_mlp2(const float* __restrict__ g2,
                                                 const float* __restrict__ b2) {
    __shared__ __align__(16) float hs[64*64];    // [kk][nl], 16 KB
    __shared__ float sc[256], sh[256];
    __shared__ float s3s[64], q3s[64];
    int tid = threadIdx.x;
    if (tid < 256) {
        double cnt = (double)(Bb*Nn);
        double mu  = g_s2[tid] / cnt;
        double var = g_ss2[tid] / cnt - mu*mu;
        float s = g2[tid] * rsqrtf((float)var + EPSc);
        sc[tid] = s;
        sh[tid] = b2[tid] - (float)mu * s;
    }
    if (tid < 64) { s3s[tid] = 0.f; q3s[tid] = 0.f; }
    __syncthreads();

    int b  = blockIdx.x >> 5;
    int n0 = (blockIdx.x & 31) << 6;    // 64 n per block
    int nc = tid & 7, cc = tid >> 3;    // n: nc*8..+7 ; c: cc*2..+1
    unsigned long long acc[2][4];
    #pragma unroll
    for (int i = 0; i < 2; i++)
        #pragma unroll
        for (int j = 0; j < 4; j++) acc[i][j] = 0ull;

    for (int k0 = 0; k0 < 256; k0 += 64) {
        for (int i = tid; i < 4096; i += 256) {
            int kk = i >> 6, nl = i & 63;
            int c = k0 + kk;
            float v = g_y[(size_t)(b*256 + c)*2048 + n0 + nl];
            hs[i] = fmaxf(0.f, fmaf(v, sc[c], sh[c]));
        }
        __syncthreads();
        #pragma unroll 4
        for (int kk = 0; kk < 64; kk++) {
            ulonglong2 w = __ldg((const ulonglong2*)&g_w3d[(k0+kk)*128 + cc*4]);
            const ulonglong2* hp = (const ulonglong2*)&hs[kk*64 + nc*8];
            ulonglong2 h0 = hp[0], h1 = hp[1];
            unsigned long long hd[4] = {h0.x, h0.y, h1.x, h1.y};
            #pragma unroll
            for (int np = 0; np < 4; np++) FFMA2(acc[0][np], w.x, hd[np]);
            #pragma unroll
            for (int np = 0; np < 4; np++) FFMA2(acc[1][np], w.y, hd[np]);
        }
        __syncthreads();
    }
    #pragma unroll
    for (int ci = 0; ci < 2; ci++) {
        int c = cc*2 + ci;
        float v0 = f2lo(acc[ci][0]), v1 = f2hi(acc[ci][0]);
        float v2 = f2lo(acc[ci][1]), v3 = f2hi(acc[ci][1]);
        float v4 = f2lo(acc[ci][2]), v5 = f2hi(acc[ci][2]);
        float v6 = f2lo(acc[ci][3]), v7 = f2hi(acc[ci][3]);
        float s = ((v0+v1)+(v2+v3)) + ((v4+v5)+(v6+v7));
        float q = fmaf(v0,v0, fmaf(v1,v1, fmaf(v2,v2, fmaf(v3,v3,
                  fmaf(v4,v4, fmaf(v5,v5, fmaf(v6,v6, v7*v7)))))));
        atomicAdd(&s3s[c], s); atomicAdd(&q3s[c], q);
        float* zp = &g_z[(size_t)(b*64 + c)*2048 + n0 + nc*8];
        *(float4*)zp       = make_float4(v0, v1, v2, v3);
        *(float4*)(zp + 4) = make_float4(v4, v5, v6, v7);
    }
    __syncthreads();
    if (tid < 64) {
        atomicAdd(&g_s3[tid],  (double)s3s[tid]);
        atomicAdd(&g_ss3[tid], (double)q3s[tid]);
    }
}

// ---------------- K_out: relu(bn3(z) + f) ----------------
__global__ void __launch_bounds__(256) k_out(const float* __restrict__ f,
                                             const float* __restrict__ g3,
                                             const float* __restrict__ b3,
                                             float* __restrict__ out) {
    __shared__ float sc[64], sh[64];
    int tid = threadIdx.x;
    if (tid < 64) {
        double cnt = (double)(Bb*Nn);
        double mu  = g_s3[tid] / cnt;
        double var = g_ss3[tid] / cnt - mu*mu;
        float s = g3[tid] * rsqrtf((float)var + EPSc);
        sc[tid] = s;
        sh[tid] = b3[tid] - (float)mu * s;
    }
    __syncthreads();
    int i = blockIdx.x * 256 + tid;     // float4 index
    int base = i * 4;
    int c = (base >> 11) & 63;
    float4 z  = *(const float4*)&g_z[base];
    float4 fv = *(const float4*)&f[base];
    float4 o;
    o.x = fmaxf(0.f, fmaf(z.x, sc[c], sh[c]) + fv.x);
    o.y = fmaxf(0.f, fmaf(z.y, sc[c], sh[c]) + fv.y);
    o.z = fmaxf(0.f, fmaf(z.z, sc[c], sh[c]) + fv.z);
    o.w = fmaxf(0.f, fmaf(z.w, sc[c], sh[c]) + fv.w);
    *(float4*)&out[base] = o;
}

// ---------------- launch ----------------
extern "C" void kernel_launch(void* const* d_in, const int* in_sizes, int n_in,
                              void* d_out, int out_size) {
    const float* p  = (const float*)d_in[0];
    const float* f  = (const float*)d_in[1];
    const float* w1 = (const float*)d_in[2];
    const float* g1 = (const float*)d_in[3];
    const float* b1 = (const float*)d_in[4];
    const float* w2 = (const float*)d_in[5];
    const float* g2 = (const float*)d_in[6];
    const float* b2 = (const float*)d_in[7];
    const float* w3 = (const float*)d_in[8];
    const float* g3 = (const float*)d_in[9];
    const float* b3 = (const float*)d_in[10];
    float* out = (float*)d_out;

    k_gfeat<<<512,  256>>>(f, w1, w2, w3);
    k_ballq<<<1024, 512>>>(p);
    k_agg  <<<2048, 256>>>(p, w1);
    k_mlp1 <<<256,  256>>>(g1, b1);
    k_mlp2 <<<256,  256>>>(g2, b2);
    k_out  <<<1024, 256>>>(f, g3, b3, out);
}

// round 6
// speedup vs baseline: 1.4105x; 1.0184x over previous
#include <cuda_runtime.h>

#define Bb   8
#define Nn   2048
#define Cc   64
#define MIDm 256
#define KK   16
#define R2c  0.0225f
#define EPSc 1e-5f

// ---------------- scratch (device globals, no allocation) ----------------
__device__ __align__(16) int    g_idx[Bb*Nn*KK];      // [b][n][16]
__device__ __align__(16) float  g_feat[Bb*Nn*Cc];     // [b][n][c]  = w1[:,3:]@f
__device__ __align__(16) float  g_m[Bb*Cc*Nn];        // [b][c][n]  = max_k x
__device__ __align__(16) float  g_y[Bb*MIDm*Nn];      // [b][c][n]
__device__ __align__(16) float  g_z[Bb*Cc*Nn];        // [b][c][n]
__device__ __align__(16) float  g_w2t[Cc*MIDm];       // [k][o] = w2[o][k]
__device__ __align__(16) float  g_w3t[MIDm*Cc];       // [k][c] = w3[c][k]
__device__ double g_s1[Cc],   g_ss1[Cc];
__device__ double g_s2[MIDm], g_ss2[MIDm];
__device__ double g_s3[Cc],   g_ss3[Cc];

// ---------------- K_gfeat: g[b][n][c] = sum_cp w1[c][3+cp] * f[b][cp][n] ----------------
// Blocks < 64 additionally perform prep (weight transposes + stat zeroing).
__global__ void __launch_bounds__(256) k_gfeat(const float* __restrict__ f,
                                               const float* __restrict__ w1,
                                               const float* __restrict__ w2,
                                               const float* __restrict__ w3) {
    __shared__ __align__(16) float w1t[64*68];   // [cp][c], padded
    __shared__ __align__(16) float fs[64*32];    // [cp][nl]
    __shared__ __align__(16) float gs[32*68];    // [nl][c], padded
    int tid = threadIdx.x;
    int b  = blockIdx.x >> 6;
    int n0 = (blockIdx.x & 63) << 5;

    if (blockIdx.x < 64) {
        int i = blockIdx.x * 256 + tid;
        if (i < Cc*MIDm) {
            int o = i >> 6, k = i & 63;           // w2: (256,64) row-major
            g_w2t[k*MIDm + o] = w2[i];
            int c = i >> 8, kk = i & 255;         // w3: (64,256) row-major
            g_w3t[kk*Cc + c] = w3[i];
        }
        if (i < Cc)   { g_s1[i]=0.0; g_ss1[i]=0.0; g_s3[i]=0.0; g_ss3[i]=0.0; }
        if (i < MIDm) { g_s2[i]=0.0; g_ss2[i]=0.0; }
    }

    for (int i = tid; i < 64*64; i += 256) {
        int c = i >> 6, cp = i & 63;
        w1t[cp*68 + c] = w1[c*67 + 3 + cp];
    }
    for (int i = tid; i < 64*32; i += 256) {
        int cp = i >> 5, nl = i & 31;
        fs[i] = f[(b*64 + cp)*2048 + n0 + nl];
    }
    __syncthreads();

    int nl = tid & 31, cg = tid >> 5;
    float acc[8];
    #pragma unroll
    for (int i = 0; i < 8; i++) acc[i] = 0.f;

    #pragma unroll 8
    for (int cp = 0; cp < 64; cp++) {
        float fv = fs[cp*32 + nl];
        float4 wa = *(const float4*)&w1t[cp*68 + cg*8];
        float4 wb = *(const float4*)&w1t[cp*68 + cg*8 + 4];
        acc[0] = fmaf(wa.x, fv, acc[0]);
        acc[1] = fmaf(wa.y, fv, acc[1]);
        acc[2] = fmaf(wa.z, fv, acc[2]);
        acc[3] = fmaf(wa.w, fv, acc[3]);
        acc[4] = fmaf(wb.x, fv, acc[4]);
        acc[5] = fmaf(wb.y, fv, acc[5]);
        acc[6] = fmaf(wb.z, fv, acc[6]);
        acc[7] = fmaf(wb.w, fv, acc[7]);
    }
    #pragma unroll
    for (int i = 0; i < 8; i++) gs[nl*68 + cg*8 + i] = acc[i];
    __syncthreads();
    for (int i = tid; i < 2048; i += 256) {
        int nn = i >> 6, c = i & 63;
        g_feat[(b*2048 + n0 + nn)*64 + c] = gs[nn*68 + c];
    }
}

// ---------------- K_ballq: warp-per-point ascending scan, early exit ----------------
__global__ void __launch_bounds__(512) k_ballq(const float* __restrict__ p) {
    __shared__ float px[2048], py[2048], pz[2048];
    __shared__ int   ob[16][16];
    int tid = threadIdx.x;
    int b  = blockIdx.x >> 7;
    int n0 = (blockIdx.x & 127) << 4;

    for (int i = tid; i < 2048; i += 512) {
        const float* pp = p + (size_t)(b*2048 + i)*3;
        px[i] = pp[0]; py[i] = pp[1]; pz[i] = pp[2];
    }
    __syncthreads();

    int w = tid >> 5, lane = tid & 31;
    int n = n0 + w;
    float qx = px[n], qy = py[n], qz = pz[n];
    int cnt = 0;
    for (int j0 = 0; j0 < 2048; j0 += 32) {
        int j = j0 + lane;
        float dx = __fsub_rn(px[j], qx);
        float dy = __fsub_rn(py[j], qy);
        float dz = __fsub_rn(pz[j], qz);
        float d2 = __fadd_rn(__fadd_rn(__fmul_rn(dx,dx), __fmul_rn(dy,dy)), __fmul_rn(dz,dz));
        bool q = d2 < R2c;
        unsigned mask = __ballot_sync(0xffffffffu, q);
        if (mask) {
            int r = cnt + __popc(mask & ((1u << lane) - 1u));
            if (q && r < 16) ob[w][r] = j;
            cnt += __popc(mask);
            if (cnt >= 16) break;
        }
    }
    __syncwarp();
    if (cnt < 16) {
        int first = ob[w][0];
        if (lane >= cnt && lane < 16) ob[w][lane] = first;
        __syncwarp();
    }
    if (lane < 16) g_idx[(b*2048 + n)*16 + lane] = ob[w][lane];
}

// ---------------- K_agg: x = g[j] + w1p@dp ; stats1 + max over K ----------------
__global__ void __launch_bounds__(256) k_agg(const float* __restrict__ p,
                                             const float* __restrict__ w1) {
    __shared__ float ms[64*8];
    __shared__ float s1s[64], q1s[64];
    int tid = threadIdx.x;
    if (tid < 64) { s1s[tid] = 0.f; q1s[tid] = 0.f; }
    __syncthreads();

    int b  = blockIdx.x >> 8;
    int n0 = (blockIdx.x & 255) << 3;
    int w = tid >> 5, lane = tid & 31;
    int n = n0 + w;
    int c0 = lane * 2;

    float wx0 = w1[c0*67+0],     wy0 = w1[c0*67+1],     wz0 = w1[c0*67+2];
    float wx1 = w1[(c0+1)*67+0], wy1 = w1[(c0+1)*67+1], wz1 = w1[(c0+1)*67+2];
    const float* pc = p + (size_t)(b*2048 + n)*3;
    float cx = pc[0], cy = pc[1], cz = pc[2];
    int jr = g_idx[(b*2048 + n)*16 + (lane & 15)];

    float dxr = 0.f, dyr = 0.f, dzr = 0.f;
    if (lane < 16) {
        const float* pj = p + (size_t)(b*2048 + jr)*3;
        dxr = pj[0] - cx; dyr = pj[1] - cy; dzr = pj[2] - cz;
    }

    int js[16];
    #pragma unroll
    for (int k = 0; k < 16; k++) js[k] = __shfl_sync(0xffffffffu, jr, k);

    float2 gv[16];
    #pragma unroll
    for (int k = 0; k < 16; k++)
        gv[k] = __ldg((const float2*)(g_feat + (size_t)(b*2048 + js[k])*64 + c0));

    float mx0 = -3.402823466e38f, mx1 = -3.402823466e38f;
    float s0 = 0.f, q0 = 0.f, s1v = 0.f, q1v = 0.f;
    #pragma unroll
    for (int k = 0; k < 16; k++) {
        float dx = __shfl_sync(0xffffffffu, dxr, k);
        float dy = __shfl_sync(0xffffffffu, dyr, k);
        float dz = __shfl_sync(0xffffffffu, dzr, k);
        float v0 = fmaf(wx0, dx, fmaf(wy0, dy, fmaf(wz0, dz, gv[k].x)));
        float v1 = fmaf(wx1, dx, fmaf(wy1, dy, fmaf(wz1, dz, gv[k].y)));
        mx0 = fmaxf(mx0, v0); mx1 = fmaxf(mx1, v1);
        s0 += v0;  q0  = fmaf(v0, v0, q0);
        s1v += v1; q1v = fmaf(v1, v1, q1v);
    }
    ms[c0*8 + w]     = mx0;
    ms[(c0+1)*8 + w] = mx1;
    atomicAdd(&s1s[c0],   s0);  atomicAdd(&q1s[c0],   q0);
    atomicAdd(&s1s[c0+1], s1v); atomicAdd(&q1s[c0+1], q1v);
    __syncthreads();
    for (int i = tid; i < 512; i += 256) {
        int c = i >> 3, nl = i & 7;
        g_m[(b*64 + c)*2048 + n0 + nl] = ms[i];
    }
    if (tid < 64) {
        atomicAdd(&g_s1[tid],  (double)s1s[tid]);
        atomicAdd(&g_ss1[tid], (double)q1s[tid]);
    }
}

// ---------------- K_mlp1: y = w2 @ relu(bn1(m)) ; stats2 ----------------
// Occupancy-first tiling: block = 64c x 64n, thread = 4c x 4n (16 acc regs).
// grid = 8b x 4ct x 32nt = 1024 blocks.
__global__ void __launch_bounds__(256) k_mlp1(const float* __restrict__ g1,
                                              const float* __restrict__ b1) {
    __shared__ __align__(16) float hs[64*64];    // [k][nl] 16 KB
    __shared__ __align__(16) float ws[64*64];    // [k][cl] 16 KB
    __shared__ float sc[64], sh[64];
    __shared__ float s2s[64], q2s[64];
    int tid = threadIdx.x;
    int b  = blockIdx.x >> 7;           // 128 blocks per batch
    int ct = (blockIdx.x >> 5) & 3;
    int n0 = (blockIdx.x & 31) << 6;
    int c0 = ct << 6;

    if (tid < 64) {
        double cnt = (double)(Bb*Nn*KK);
        double mu  = g_s1[tid] / cnt;
        double var = g_ss1[tid] / cnt - mu*mu;
        float s = g1[tid] * rsqrtf((float)var + EPSc);
        sc[tid] = s;
        sh[tid] = b1[tid] - (float)mu * s;
        s2s[tid] = 0.f; q2s[tid] = 0.f;
    }
    __syncthreads();

    for (int i = tid; i < 4096; i += 256) {
        int k = i >> 6, nl = i & 63;
        float v = g_m[(b*64 + k)*2048 + n0 + nl];
        hs[i] = fmaxf(0.f, fmaf(v, sc[k], sh[k]));
    }
    for (int i = tid; i < 4096; i += 256) {
        int k = i >> 6, cl = i & 63;
        ws[i] = g_w2t[k*256 + c0 + cl];
    }
    __syncthreads();

    int nc = tid & 15, cc = tid >> 4;   // n: nc*4..+3 ; c: cc*4..+3
    float acc[4][4];
    #pragma unroll
    for (int i = 0; i < 4; i++)
        #pragma unroll
        for (int j = 0; j < 4; j++) acc[i][j] = 0.f;

    #pragma unroll 8
    for (int k = 0; k < 64; k++) {
        float4 h = *(const float4*)&hs[k*64 + nc*4];
        float4 w = *(const float4*)&ws[k*64 + cc*4];
        float hv[4] = {h.x, h.y, h.z, h.w};
        float wv[4] = {w.x, w.y, w.z, w.w};
        #pragma unroll
        for (int ci = 0; ci < 4; ci++)
            #pragma unroll
            for (int nj = 0; nj < 4; nj++)
                acc[ci][nj] = fmaf(wv[ci], hv[nj], acc[ci][nj]);
    }
    #pragma unroll
    for (int ci = 0; ci < 4; ci++) {
        int cl = cc*4 + ci;
        float v0 = acc[ci][0], v1 = acc[ci][1], v2 = acc[ci][2], v3 = acc[ci][3];
        float s = (v0+v1)+(v2+v3);
        float q = fmaf(v0,v0, fmaf(v1,v1, fmaf(v2,v2, v3*v3)));
        atomicAdd(&s2s[cl], s); atomicAdd(&q2s[cl], q);
        *(float4*)&g_y[(size_t)(b*256 + c0 + cl)*2048 + n0 + nc*4] =
            make_float4(v0, v1, v2, v3);
    }
    __syncthreads();
    if (tid < 64) {
        atomicAdd(&g_s2[c0 + tid],  (double)s2s[tid]);
        atomicAdd(&g_ss2[c0 + tid], (double)q2s[tid]);
    }
}

// ---------------- K_mlp2: z = w3 @ relu(bn2(y)) ; stats3 ----------------
// Block = 64c x 64n, thread = 4c x 4n, K=256 chunked by 64. grid = 8b x 32nt = 256.
__global__ void __launch_bounds__(256) k_mlp2(const float* __restrict__ g2,
                                              const float* __restrict__ b2) {
    __shared__ __align__(16) float hs[64*64];    // [kk][nl] 16 KB
    __shared__ __align__(16) float ws[64*64];    // [kk][cl] 16 KB
    __shared__ float sc[256], sh[256];
    __shared__ float s3s[64], q3s[64];
    int tid = threadIdx.x;
    int b  = blockIdx.x >> 5;
    int n0 = (blockIdx.x & 31) << 6;

    {
        double cnt = (double)(Bb*Nn);
        double mu  = g_s2[tid] / cnt;
        double var = g_ss2[tid] / cnt - mu*mu;
        float s = g2[tid] * rsqrtf((float)var + EPSc);
        sc[tid] = s;
        sh[tid] = b2[tid] - (float)mu * s;
    }
    if (tid < 64) { s3s[tid] = 0.f; q3s[tid] = 0.f; }
    __syncthreads();

    int nc = tid & 15, cc = tid >> 4;   // n: nc*4..+3 ; c: cc*4..+3
    float acc[4][4];
    #pragma unroll
    for (int i = 0; i < 4; i++)
        #pragma unroll
        for (int j = 0; j < 4; j++) acc[i][j] = 0.f;

    for (int k0 = 0; k0 < 256; k0 += 64) {
        for (int i = tid; i < 4096; i += 256) {
            int kk = i >> 6, nl = i & 63;
            int ch = k0 + kk;
            float v = g_y[(size_t)(b*256 + ch)*2048 + n0 + nl];
            hs[i] = fmaxf(0.f, fmaf(v, sc[ch], sh[ch]));
        }
        for (int i = tid; i < 4096; i += 256) {
            int kk = i >> 6, cl = i & 63;
            ws[i] = g_w3t[(k0 + kk)*64 + cl];
        }
        __syncthreads();
        #pragma unroll 8
        for (int kk = 0; kk < 64; kk++) {
            float4 h = *(const float4*)&hs[kk*64 + nc*4];
            float4 w = *(const float4*)&ws[kk*64 + cc*4];
            float hv[4] = {h.x, h.y, h.z, h.w};
            float wv[4] = {w.x, w.y, w.z, w.w};
            #pragma unroll
            for (int ci = 0; ci < 4; ci++)
                #pragma unroll
                for (int nj = 0; nj < 4; nj++)
                    acc[ci][nj] = fmaf(wv[ci], hv[nj], acc[ci][nj]);
        }
        __syncthreads();
    }
    #pragma unroll
    for (int ci = 0; ci < 4; ci++) {
        int cl = cc*4 + ci;
        float v0 = acc[ci][0], v1 = acc[ci][1], v2 = acc[ci][2], v3 = acc[ci][3];
        float s = (v0+v1)+(v2+v3);
        float q = fmaf(v0,v0, fmaf(v1,v1, fmaf(v2,v2, v3*v3)));
        atomicAdd(&s3s[cl], s); atomicAdd(&q3s[cl], q);
        *(float4*)&g_z[(size_t)(b*64 + cl)*2048 + n0 + nc*4] =
            make_float4(v0, v1, v2, v3);
    }
    __syncthreads();
    if (tid < 64) {
        atomicAdd(&g_s3[tid],  (double)s3s[tid]);
        atomicAdd(&g_ss3[tid], (double)q3s[tid]);
    }
}

// ---------------- K_out: relu(bn3(z) + f) ----------------
__global__ void __launch_bounds__(256) k_out(const float* __restrict__ f,
                                             const float* __restrict__ g3,
                                             const float* __restrict__ b3,
                                             float* __restrict__ out) {
    __shared__ float sc[64], sh[64];
    int tid = threadIdx.x;
    if (tid < 64) {
        double cnt = (double)(Bb*Nn);
        double mu  = g_s3[tid] / cnt;
        double var = g_ss3[tid] / cnt - mu*mu;
        float s = g3[tid] * rsqrtf((float)var + EPSc);
        sc[tid] = s;
        sh[tid] = b3[tid] - (float)mu * s;
    }
    __syncthreads();
    int i = blockIdx.x * 256 + tid;
    int base = i * 4;
    int c = (base >> 11) & 63;
    float4 z  = *(const float4*)&g_z[base];
    float4 fv = *(const float4*)&f[base];
    float4 o;
    o.x = fmaxf(0.f, fmaf(z.x, sc[c], sh[c]) + fv.x);
    o.y = fmaxf(0.f, fmaf(z.y, sc[c], sh[c]) + fv.y);
    o.z = fmaxf(0.f, fmaf(z.z, sc[c], sh[c]) + fv.z);
    o.w = fmaxf(0.f, fmaf(z.w, sc[c], sh[c]) + fv.w);
    *(float4*)&out[base] = o;
}

// ---------------- launch ----------------
extern "C" void kernel_launch(void* const* d_in, const int* in_sizes, int n_in,
                              void* d_out, int out_size) {
    const float* p  = (const float*)d_in[0];
    const float* f  = (const float*)d_in[1];
    const float* w1 = (const float*)d_in[2];
    const float* g1 = (const float*)d_in[3];
    const float* b1 = (const float*)d_in[4];
    const float* w2 = (const float*)d_in[5];
    const float* g2 = (const float*)d_in[6];
    const float* b2 = (const float*)d_in[7];
    const float* w3 = (const float*)d_in[8];
    const float* g3 = (const float*)d_in[9];
    const float* b3 = (const float*)d_in[10];
    float* out = (float*)d_out;

    k_gfeat<<<512,  256>>>(f, w1, w2, w3);
    k_ballq<<<1024, 512>>>(p);
    k_agg  <<<2048, 256>>>(p, w1);
    k_mlp1 <<<1024, 256>>>(g1, b1);
    k_mlp2 <<<256,  256>>>(g2, b2);
    k_out  <<<1024, 256>>>(f, g3, b3, out);
}

// round 7
// speedup vs baseline: 1.7192x; 1.2188x over previous
#include <cuda_runtime.h>
#include <cuda_bf16.h>
#include <cstdint>

#define Bb   8
#define Nn   2048
#define Cc   64
#define MIDm 256
#define KK   16
#define R2c  0.0225f
#define EPSc 1e-5f

// ---------------- scratch (device globals, no allocation) ----------------
__device__ __align__(16) int    g_idx[Bb*Nn*KK];      // [b][n][16]
__device__ __align__(16) float  g_feat[Bb*Nn*Cc];     // [b][n][c]  = w1[:,3:]@f
__device__ __align__(16) float  g_m[Bb*Cc*Nn];        // [b][c][n]  = max_k x
__device__ __align__(16) float  g_y[Bb*MIDm*Nn];      // [b][c][n]
__device__ __align__(16) float  g_z[Bb*Cc*Nn];        // [b][c][n]
// split-bf16 weights (same layout as source, no transpose needed)
__device__ __align__(16) __nv_bfloat16 g_w2h[MIDm*Cc], g_w2l[MIDm*Cc];   // [o=256][k=64]
__device__ __align__(16) __nv_bfloat16 g_w3h[Cc*MIDm], g_w3l[Cc*MIDm];   // [c=64][k=256]
__device__ double g_s1[Cc],   g_ss1[Cc];
__device__ double g_s2[MIDm], g_ss2[MIDm];
__device__ double g_s3[Cc],   g_ss3[Cc];

// ---------------- mma/ldmatrix helpers ----------------
__device__ __forceinline__ uint32_t smem_u32(const void* p) {
    uint32_t r;
    asm("{ .reg .u64 t; cvta.to.shared.u64 t, %1; cvt.u32.u64 %0, t; }" : "=r"(r) : "l"(p));
    return r;
}
__device__ __forceinline__ void ldmA(uint32_t* a, uint32_t addr) {   // x4 non-trans
    asm volatile("ldmatrix.sync.aligned.m8n8.x4.shared.b16 {%0,%1,%2,%3}, [%4];"
                 : "=r"(a[0]), "=r"(a[1]), "=r"(a[2]), "=r"(a[3]) : "r"(addr));
}
__device__ __forceinline__ void ldmB(uint32_t* b2, uint32_t addr) {  // x2 trans
    asm volatile("ldmatrix.sync.aligned.m8n8.x2.trans.shared.b16 {%0,%1}, [%2];"
                 : "=r"(b2[0]), "=r"(b2[1]) : "r"(addr));
}
__device__ __forceinline__ void mma16816(float* d, const uint32_t* a, const uint32_t* b2) {
    asm volatile(
        "mma.sync.aligned.m16n8k16.row.col.f32.bf16.bf16.f32 "
        "{%0,%1,%2,%3}, {%4,%5,%6,%7}, {%8,%9}, {%0,%1,%2,%3};"
        : "+f"(d[0]), "+f"(d[1]), "+f"(d[2]), "+f"(d[3])
        : "r"(a[0]), "r"(a[1]), "r"(a[2]), "r"(a[3]), "r"(b2[0]), "r"(b2[1]));
}
__device__ __forceinline__ void split_bf16(float v, __nv_bfloat16& h, __nv_bfloat16& l) {
    h = __float2bfloat16_rn(v);
    l = __float2bfloat16_rn(v - __bfloat162float(h));
}

// ---------------- K_gfeat (+prep in blocks<64) ----------------
__global__ void __launch_bounds__(256) k_gfeat(const float* __restrict__ f,
                                               const float* __restrict__ w1,
                                               const float* __restrict__ w2,
                                               const float* __restrict__ w3) {
    __shared__ __align__(16) float w1t[64*68];
    __shared__ __align__(16) float fs[64*32];
    __shared__ __align__(16) float gs[32*68];
    int tid = threadIdx.x;
    int b  = blockIdx.x >> 6;
    int n0 = (blockIdx.x & 63) << 5;

    if (blockIdx.x < 64) {
        int i = blockIdx.x * 256 + tid;          // 0..16383
        { __nv_bfloat16 h, l; split_bf16(w2[i], h, l); g_w2h[i] = h; g_w2l[i] = l; }
        { __nv_bfloat16 h, l; split_bf16(w3[i], h, l); g_w3h[i] = h; g_w3l[i] = l; }
        if (i < Cc)   { g_s1[i]=0.0; g_ss1[i]=0.0; g_s3[i]=0.0; g_ss3[i]=0.0; }
        if (i < MIDm) { g_s2[i]=0.0; g_ss2[i]=0.0; }
    }

    for (int i = tid; i < 64*64; i += 256) {
        int c = i >> 6, cp = i & 63;
        w1t[cp*68 + c] = w1[c*67 + 3 + cp];
    }
    for (int i = tid; i < 64*32; i += 256) {
        int cp = i >> 5, nl = i & 31;
        fs[i] = f[(b*64 + cp)*2048 + n0 + nl];
    }
    __syncthreads();

    int nl = tid & 31, cg = tid >> 5;
    float acc[8];
    #pragma unroll
    for (int i = 0; i < 8; i++) acc[i] = 0.f;

    #pragma unroll 8
    for (int cp = 0; cp < 64; cp++) {
        float fv = fs[cp*32 + nl];
        float4 wa = *(const float4*)&w1t[cp*68 + cg*8];
        float4 wb = *(const float4*)&w1t[cp*68 + cg*8 + 4];
        acc[0] = fmaf(wa.x, fv, acc[0]);
        acc[1] = fmaf(wa.y, fv, acc[1]);
        acc[2] = fmaf(wa.z, fv, acc[2]);
        acc[3] = fmaf(wa.w, fv, acc[3]);
        acc[4] = fmaf(wb.x, fv, acc[4]);
        acc[5] = fmaf(wb.y, fv, acc[5]);
        acc[6] = fmaf(wb.z, fv, acc[6]);
        acc[7] = fmaf(wb.w, fv, acc[7]);
    }
    #pragma unroll
    for (int i = 0; i < 8; i++) gs[nl*68 + cg*8 + i] = acc[i];
    __syncthreads();
    for (int i = tid; i < 2048; i += 256) {
        int nn = i >> 6, c = i & 63;
        g_feat[(b*2048 + n0 + nn)*64 + c] = gs[nn*68 + c];
    }
}

// ---------------- K_ballq ----------------
__global__ void __launch_bounds__(512) k_ballq(const float* __restrict__ p) {
    __shared__ float px[2048], py[2048], pz[2048];
    __shared__ int   ob[16][16];
    int tid = threadIdx.x;
    int b  = blockIdx.x >> 7;
    int n0 = (blockIdx.x & 127) << 4;

    for (int i = tid; i < 2048; i += 512) {
        const float* pp = p + (size_t)(b*2048 + i)*3;
        px[i] = pp[0]; py[i] = pp[1]; pz[i] = pp[2];
    }
    __syncthreads();

    int w = tid >> 5, lane = tid & 31;
    int n = n0 + w;
    float qx = px[n], qy = py[n], qz = pz[n];
    int cnt = 0;
    for (int j0 = 0; j0 < 2048; j0 += 32) {
        int j = j0 + lane;
        float dx = __fsub_rn(px[j], qx);
        float dy = __fsub_rn(py[j], qy);
        float dz = __fsub_rn(pz[j], qz);
        float d2 = __fadd_rn(__fadd_rn(__fmul_rn(dx,dx), __fmul_rn(dy,dy)), __fmul_rn(dz,dz));
        bool q = d2 < R2c;
        unsigned mask = __ballot_sync(0xffffffffu, q);
        if (mask) {
            int r = cnt + __popc(mask & ((1u << lane) - 1u));
            if (q && r < 16) ob[w][r] = j;
            cnt += __popc(mask);
            if (cnt >= 16) break;
        }
    }
    __syncwarp();
    if (cnt < 16) {
        int first = ob[w][0];
        if (lane >= cnt && lane < 16) ob[w][lane] = first;
        __syncwarp();
    }
    if (lane < 16) g_idx[(b*2048 + n)*16 + lane] = ob[w][lane];
}

// ---------------- K_agg ----------------
__global__ void __launch_bounds__(256) k_agg(const float* __restrict__ p,
                                             const float* __restrict__ w1) {
    __shared__ float ms[64*8];
    __shared__ float s1s[64], q1s[64];
    int tid = threadIdx.x;
    if (tid < 64) { s1s[tid] = 0.f; q1s[tid] = 0.f; }
    __syncthreads();

    int b  = blockIdx.x >> 8;
    int n0 = (blockIdx.x & 255) << 3;
    int w = tid >> 5, lane = tid & 31;
    int n = n0 + w;
    int c0 = lane * 2;

    float wx0 = w1[c0*67+0],     wy0 = w1[c0*67+1],     wz0 = w1[c0*67+2];
    float wx1 = w1[(c0+1)*67+0], wy1 = w1[(c0+1)*67+1], wz1 = w1[(c0+1)*67+2];
    const float* pc = p + (size_t)(b*2048 + n)*3;
    float cx = pc[0], cy = pc[1], cz = pc[2];
    int jr = g_idx[(b*2048 + n)*16 + (lane & 15)];

    float dxr = 0.f, dyr = 0.f, dzr = 0.f;
    if (lane < 16) {
        const float* pj = p + (size_t)(b*2048 + jr)*3;
        dxr = pj[0] - cx; dyr = pj[1] - cy; dzr = pj[2] - cz;
    }

    int js[16];
    #pragma unroll
    for (int k = 0; k < 16; k++) js[k] = __shfl_sync(0xffffffffu, jr, k);

    float2 gv[16];
    #pragma unroll
    for (int k = 0; k < 16; k++)
        gv[k] = __ldg((const float2*)(g_feat + (size_t)(b*2048 + js[k])*64 + c0));

    float mx0 = -3.402823466e38f, mx1 = -3.402823466e38f;
    float s0 = 0.f, q0 = 0.f, s1v = 0.f, q1v = 0.f;
    #pragma unroll
    for (int k = 0; k < 16; k++) {
        float dx = __shfl_sync(0xffffffffu, dxr, k);
        float dy = __shfl_sync(0xffffffffu, dyr, k);
        float dz = __shfl_sync(0xffffffffu, dzr, k);
        float v0 = fmaf(wx0, dx, fmaf(wy0, dy, fmaf(wz0, dz, gv[k].x)));
        float v1 = fmaf(wx1, dx, fmaf(wy1, dy, fmaf(wz1, dz, gv[k].y)));
        mx0 = fmaxf(mx0, v0); mx1 = fmaxf(mx1, v1);
        s0 += v0;  q0  = fmaf(v0, v0, q0);
        s1v += v1; q1v = fmaf(v1, v1, q1v);
    }
    ms[c0*8 + w]     = mx0;
    ms[(c0+1)*8 + w] = mx1;
    atomicAdd(&s1s[c0],   s0);  atomicAdd(&q1s[c0],   q0);
    atomicAdd(&s1s[c0+1], s1v); atomicAdd(&q1s[c0+1], q1v);
    __syncthreads();
    for (int i = tid; i < 512; i += 256) {
        int c = i >> 3, nl = i & 7;
        g_m[(b*64 + c)*2048 + n0 + nl] = ms[i];
    }
    if (tid < 64) {
        atomicAdd(&g_s1[tid],  (double)s1s[tid]);
        atomicAdd(&g_ss1[tid], (double)q1s[tid]);
    }
}

// ---------------- K_mlp1 (HMMA): y[c0..c0+128, n0..n0+128] = w2 @ relu(bn1(m)) ----------------
// smem layout (bytes): sc@0[256] sh@256[256] s2s@512[512] q2s@1024[512]
//   A_hi@2048 (128x72 bf16 = 18432)  A_lo@20480  B_hi@38912 (64x136 bf16 = 17408)  B_lo@56320
#define M1_AH 2048
#define M1_AL 20480
#define M1_BH 38912
#define M1_BL 56320
#define M1_SMEM 73728
#define LDA1 72
#define LDB1 136
__global__ void __launch_bounds__(256) k_mlp1(const float* __restrict__ g1,
                                              const float* __restrict__ b1) {
    extern __shared__ __align__(16) char smem[];
    uint32_t sb = smem_u32(smem);
    float* sc  = (float*)(smem);
    float* sh  = (float*)(smem + 256);
    float* s2s = (float*)(smem + 512);
    float* q2s = (float*)(smem + 1024);
    int tid = threadIdx.x, wid = tid >> 5, lane = tid & 31;
    int b  = blockIdx.x >> 5;
    int ct = (blockIdx.x >> 4) & 1;
    int nt = blockIdx.x & 15;
    int c0 = ct << 7, n0 = nt << 7;
    int c_w = (wid & 1) << 6, n_w = (wid >> 1) << 5;

    if (tid < 64) {
        double cnt = (double)(Bb*Nn*KK);
        double mu  = g_s1[tid] / cnt;
        double var = g_ss1[tid] / cnt - mu*mu;
        float s = g1[tid] * rsqrtf((float)var + EPSc);
        sc[tid] = s;
        sh[tid] = b1[tid] - (float)mu * s;
    }
    if (tid < 128) { s2s[tid] = 0.f; q2s[tid] = 0.f; }
    __syncthreads();

    // A fill: weights [128c x 64k] hi/lo via uint4 (rows c0..c0+127)
    for (int i = tid; i < 1024; i += 256) {
        int row = i >> 3, c8 = i & 7;
        *(uint4*)(smem + M1_AH + row*(LDA1*2) + c8*16) =
            ((const uint4*)(g_w2h + (size_t)(c0 + row)*64))[c8];
        *(uint4*)(smem + M1_AL + row*(LDA1*2) + c8*16) =
            ((const uint4*)(g_w2l + (size_t)(c0 + row)*64))[c8];
    }
    // B fill: h = relu(bn1(m)) split, [64k x 128n]
    for (int i = tid; i < 8192; i += 256) {
        int k = i >> 7, n = i & 127;
        float v = g_m[(b*64 + k)*2048 + n0 + n];
        v = fmaxf(0.f, fmaf(v, sc[k], sh[k]));
        __nv_bfloat16 h, l;
        split_bf16(v, h, l);
        *(__nv_bfloat16*)(smem + M1_BH + k*(LDB1*2) + n*2) = h;
        *(__nv_bfloat16*)(smem + M1_BL + k*(LDB1*2) + n*2) = l;
    }
    __syncthreads();

    float acc[4][4][4];
    #pragma unroll
    for (int i = 0; i < 4; i++)
        #pragma unroll
        for (int j = 0; j < 4; j++)
            #pragma unroll
            for (int r = 0; r < 4; r++) acc[i][j][r] = 0.f;

    uint32_t arow = lane & 15, acol = (lane >> 4) << 3;   // ldmatrix A lane addr
    uint32_t brow = lane & 15;                            // ldmatrix B lane addr
    #pragma unroll
    for (int ks = 0; ks < 4; ks++) {
        uint32_t bh[4][2], bl[4][2];
        #pragma unroll
        for (int ntl = 0; ntl < 4; ntl++) {
            uint32_t baddr = (ks*16 + brow)*(LDB1*2) + (n_w + ntl*8)*2;
            ldmB(bh[ntl], sb + M1_BH + baddr);
            ldmB(bl[ntl], sb + M1_BL + baddr);
        }
        #pragma unroll
        for (int mt = 0; mt < 4; mt++) {
            uint32_t aaddr = (c_w + mt*16 + arow)*(LDA1*2) + (ks*16 + acol)*2;
            uint32_t ah[4], al[4];
            ldmA(ah, sb + M1_AH + aaddr);
            ldmA(al, sb + M1_AL + aaddr);
            #pragma unroll
            for (int ntl = 0; ntl < 4; ntl++) {
                mma16816(acc[mt][ntl], ah, bh[ntl]);
                mma16816(acc[mt][ntl], ah, bl[ntl]);
                mma16816(acc[mt][ntl], al, bh[ntl]);
            }
        }
    }

    // epilogue: write + stats
    int g = lane >> 2, tcol = (lane & 3) * 2;
    #pragma unroll
    for (int mt = 0; mt < 4; mt++) {
        int r0 = c_w + mt*16 + g, r1 = r0 + 8;
        float s0 = 0.f, q0 = 0.f, s1v = 0.f, q1v = 0.f;
        #pragma unroll
        for (int ntl = 0; ntl < 4; ntl++) {
            float d0 = acc[mt][ntl][0], d1 = acc[mt][ntl][1];
            float d2 = acc[mt][ntl][2], d3 = acc[mt][ntl][3];
            int col = n_w + ntl*8 + tcol;
            *(float2*)&g_y[(size_t)(b*256 + c0 + r0)*2048 + n0 + col] = make_float2(d0, d1);
            *(float2*)&g_y[(size_t)(b*256 + c0 + r1)*2048 + n0 + col] = make_float2(d2, d3);
            s0 += d0 + d1; q0 = fmaf(d0, d0, fmaf(d1, d1, q0));
            s1v += d2 + d3; q1v = fmaf(d2, d2, fmaf(d3, d3, q1v));
        }
        atomicAdd(&s2s[r0], s0);  atomicAdd(&q2s[r0], q0);
        atomicAdd(&s2s[r1], s1v); atomicAdd(&q2s[r1], q1v);
    }
    __syncthreads();
    if (tid < 128) {
        atomicAdd(&g_s2[c0 + tid],  (double)s2s[tid]);
        atomicAdd(&g_ss2[c0 + tid], (double)q2s[tid]);
    }
}

// ---------------- K_mlp2 (HMMA): z[64c, n0..n0+128] = w3 @ relu(bn2(y)) ----------------
// smem: sc@0[1024] sh@1024[1024] s3s@2048[256] q3s@2304[256] pad
//   A_hi@3072 (64x72 bf16 = 9216)  A_lo@12288  B_hi@21504 (64x136 = 17408)  B_lo@38912
#define M2_AH 3072
#define M2_AL 12288
#define M2_BH 21504
#define M2_BL 38912
#define M2_SMEM 56320
__global__ void __launch_bounds__(256) k_mlp2(const float* __restrict__ g2,
                                              const float* __restrict__ b2) {
    extern __shared__ __align__(16) char smem[];
    uint32_t sb = smem_u32(smem);
    float* sc  = (float*)(smem);
    float* sh  = (float*)(smem + 1024);
    float* s3s = (float*)(smem + 2048);
    float* q3s = (float*)(smem + 2304);
    int tid = threadIdx.x, wid = tid >> 5, lane = tid & 31;
    int b  = blockIdx.x >> 4;
    int n0 = (blockIdx.x & 15) << 7;
    int n_w = wid << 4;

    {
        double cnt = (double)(Bb*Nn);
        double mu  = g_s2[tid] / cnt;
        double var = g_ss2[tid] / cnt - mu*mu;
        float s = g2[tid] * rsqrtf((float)var + EPSc);
        sc[tid] = s;
        sh[tid] = b2[tid] - (float)mu * s;
    }
    if (tid < 64) { s3s[tid] = 0.f; q3s[tid] = 0.f; }
    __syncthreads();

    float acc[4][2][4];
    #pragma unroll
    for (int i = 0; i < 4; i++)
        #pragma unroll
        for (int j = 0; j < 2; j++)
            #pragma unroll
            for (int r = 0; r < 4; r++) acc[i][j][r] = 0.f;

    uint32_t arow = lane & 15, acol = (lane >> 4) << 3;
    uint32_t brow = lane & 15;

    for (int q = 0; q < 4; q++) {           // K chunks of 64
        int k0 = q << 6;
        // A fill: w3 [64c x 64k slice]
        for (int i = tid; i < 512; i += 256) {
            int row = i >> 3, c8 = i & 7;
            *(uint4*)(smem + M2_AH + row*(LDA1*2) + c8*16) =
                ((const uint4*)(g_w3h + (size_t)row*256 + k0))[c8];
            *(uint4*)(smem + M2_AL + row*(LDA1*2) + c8*16) =
                ((const uint4*)(g_w3l + (size_t)row*256 + k0))[c8];
        }
        // B fill: u = relu(bn2(y)) split, [64k x 128n]
        for (int i = tid; i < 8192; i += 256) {
            int kk = i >> 7, n = i & 127;
            int ch = k0 + kk;
            float v = g_y[(size_t)(b*256 + ch)*2048 + n0 + n];
            v = fmaxf(0.f, fmaf(v, sc[ch], sh[ch]));
            __nv_bfloat16 h, l;
            split_bf16(v, h, l);
            *(__nv_bfloat16*)(smem + M2_BH + kk*(LDB1*2) + n*2) = h;
            *(__nv_bfloat16*)(smem + M2_BL + kk*(LDB1*2) + n*2) = l;
        }
        __syncthreads();

        #pragma unroll
        for (int ks = 0; ks < 4; ks++) {
            uint32_t bh[2][2], bl[2][2];
            #pragma unroll
            for (int ntl = 0; ntl < 2; ntl++) {
                uint32_t baddr = (ks*16 + brow)*(LDB1*2) + (n_w + ntl*8)*2;
                ldmB(bh[ntl], sb + M2_BH + baddr);
                ldmB(bl[ntl], sb + M2_BL + baddr);
            }
            #pragma unroll
            for (int mt = 0; mt < 4; mt++) {
                uint32_t aaddr = (mt*16 + arow)*(LDA1*2) + (ks*16 + acol)*2;
                uint32_t ah[4], al[4];
                ldmA(ah, sb + M2_AH + aaddr);
                ldmA(al, sb + M2_AL + aaddr);
                #pragma unroll
                for (int ntl = 0; ntl < 2; ntl++) {
                    mma16816(acc[mt][ntl], ah, bh[ntl]);
                    mma16816(acc[mt][ntl], ah, bl[ntl]);
                    mma16816(acc[mt][ntl], al, bh[ntl]);
                }
            }
        }
        __syncthreads();
    }

    int g = lane >> 2, tcol = (lane & 3) * 2;
    #pragma unroll
    for (int mt = 0; mt < 4; mt++) {
        int r0 = mt*16 + g, r1 = r0 + 8;
        float s0 = 0.f, q0 = 0.f, s1v = 0.f, q1v = 0.f;
        #pragma unroll
        for (int ntl = 0; ntl < 2; ntl++) {
            float d0 = acc[mt][ntl][0], d1 = acc[mt][ntl][1];
            float d2 = acc[mt][ntl][2], d3 = acc[mt][ntl][3];
            int col = n_w + ntl*8 + tcol;
            *(float2*)&g_z[(size_t)(b*64 + r0)*2048 + n0 + col] = make_float2(d0, d1);
            *(float2*)&g_z[(size_t)(b*64 + r1)*2048 + n0 + col] = make_float2(d2, d3);
            s0 += d0 + d1; q0 = fmaf(d0, d0, fmaf(d1, d1, q0));
            s1v += d2 + d3; q1v = fmaf(d2, d2, fmaf(d3, d3, q1v));
        }
        atomicAdd(&s3s[r0], s0);  atomicAdd(&q3s[r0], q0);
        atomicAdd(&s3s[r1], s1v); atomicAdd(&q3s[r1], q1v);
    }
    __syncthreads();
    if (tid < 64) {
        atomicAdd(&g_s3[tid],  (double)s3s[tid]);
        atomicAdd(&g_ss3[tid], (double)q3s[tid]);
    }
}

// ---------------- K_out: relu(bn3(z) + f) ----------------
__global__ void __launch_bounds__(256) k_out(const float* __restrict__ f,
                                             const float* __restrict__ g3,
                                             const float* __restrict__ b3,
                                             float* __restrict__ out) {
    __shared__ float sc[64], sh[64];
    int tid = threadIdx.x;
    if (tid < 64) {
        double cnt = (double)(Bb*Nn);
        double mu  = g_s3[tid] / cnt;
        double var = g_ss3[tid] / cnt - mu*mu;
        float s = g3[tid] * rsqrtf((float)var + EPSc);
        sc[tid] = s;
        sh[tid] = b3[tid] - (float)mu * s;
    }
    __syncthreads();
    int i = blockIdx.x * 256 + tid;
    int base = i * 4;
    int c = (base >> 11) & 63;
    float4 z  = *(const float4*)&g_z[base];
    float4 fv = *(const float4*)&f[base];
    float4 o;
    o.x = fmaxf(0.f, fmaf(z.x, sc[c], sh[c]) + fv.x);
    o.y = fmaxf(0.f, fmaf(z.y, sc[c], sh[c]) + fv.y);
    o.z = fmaxf(0.f, fmaf(z.z, sc[c], sh[c]) + fv.z);
    o.w = fmaxf(0.f, fmaf(z.w, sc[c], sh[c]) + fv.w);
    *(float4*)&out[base] = o;
}

// ---------------- launch ----------------
extern "C" void kernel_launch(void* const* d_in, const int* in_sizes, int n_in,
                              void* d_out, int out_size) {
    const float* p  = (const float*)d_in[0];
    const float* f  = (const float*)d_in[1];
    const float* w1 = (const float*)d_in[2];
    const float* g1 = (const float*)d_in[3];
    const float* b1 = (const float*)d_in[4];
    const float* w2 = (const float*)d_in[5];
    const float* g2 = (const float*)d_in[6];
    const float* b2 = (const float*)d_in[7];
    const float* w3 = (const float*)d_in[8];
    const float* g3 = (const float*)d_in[9];
    const float* b3 = (const float*)d_in[10];
    float* out = (float*)d_out;

    cudaFuncSetAttribute(k_mlp1, cudaFuncAttributeMaxDynamicSharedMemorySize, M1_SMEM);
    cudaFuncSetAttribute(k_mlp2, cudaFuncAttributeMaxDynamicSharedMemorySize, M2_SMEM);

    k_gfeat<<<512,  256>>>(f, w1, w2, w3);
    k_ballq<<<1024, 512>>>(p);
    k_agg  <<<2048, 256>>>(p, w1);
    k_mlp1 <<<256,  256, M1_SMEM>>>(g1, b1);
    k_mlp2 <<<128,  256, M2_SMEM>>>(g2, b2);
    k_out  <<<1024, 256>>>(f, g3, b3, out);
}

// round 8
// speedup vs baseline: 1.9632x; 1.1419x over previous
#include <cuda_runtime.h>
#include <cuda_bf16.h>
#include <cstdint>

#define Bb   8
#define Nn   2048
#define Cc   64
#define MIDm 256
#define KK   16
#define R2c  0.0225f
#define EPSc 1e-5f

// ---------------- scratch (device globals, no allocation) ----------------
__device__ __align__(16) int    g_idx[Bb*Nn*KK];      // [b][n][16]
__device__ __align__(16) float  g_feat[Bb*Nn*Cc];     // [b][n][c]  = w1[:,3:]@f
__device__ __align__(16) float  g_m[Bb*Cc*Nn];        // [b][c][n]  = max_k x
__device__ __align__(16) float  g_y[Bb*MIDm*Nn];      // [b][c][n]
__device__ __align__(16) float  g_z[Bb*Cc*Nn];        // [b][c][n]
// split-bf16 weights (same layout as source, no transpose needed)
__device__ __align__(16) __nv_bfloat16 g_w2h[MIDm*Cc], g_w2l[MIDm*Cc];   // [o=256][k=64]
__device__ __align__(16) __nv_bfloat16 g_w3h[Cc*MIDm], g_w3l[Cc*MIDm];   // [c=64][k=256]
__device__ double g_s1[Cc],   g_ss1[Cc];
__device__ double g_s2[MIDm], g_ss2[MIDm];
__device__ double g_s3[Cc],   g_ss3[Cc];

// ---------------- mma/ldmatrix helpers ----------------
__device__ __forceinline__ uint32_t smem_u32(const void* p) {
    uint32_t r;
    asm("{ .reg .u64 t; cvta.to.shared.u64 t, %1; cvt.u32.u64 %0, t; }" : "=r"(r) : "l"(p));
    return r;
}
__device__ __forceinline__ void ldmA(uint32_t* a, uint32_t addr) {   // x4 non-trans
    asm volatile("ldmatrix.sync.aligned.m8n8.x4.shared.b16 {%0,%1,%2,%3}, [%4];"
                 : "=r"(a[0]), "=r"(a[1]), "=r"(a[2]), "=r"(a[3]) : "r"(addr));
}
__device__ __forceinline__ void ldmB(uint32_t* b2, uint32_t addr) {  // x2 trans
    asm volatile("ldmatrix.sync.aligned.m8n8.x2.trans.shared.b16 {%0,%1}, [%2];"
                 : "=r"(b2[0]), "=r"(b2[1]) : "r"(addr));
}
__device__ __forceinline__ void mma16816(float* d, const uint32_t* a, const uint32_t* b2) {
    asm volatile(
        "mma.sync.aligned.m16n8k16.row.col.f32.bf16.bf16.f32 "
        "{%0,%1,%2,%3}, {%4,%5,%6,%7}, {%8,%9}, {%0,%1,%2,%3};"
        : "+f"(d[0]), "+f"(d[1]), "+f"(d[2]), "+f"(d[3])
        : "r"(a[0]), "r"(a[1]), "r"(a[2]), "r"(a[3]), "r"(b2[0]), "r"(b2[1]));
}
__device__ __forceinline__ void split_bf16(float v, __nv_bfloat16& h, __nv_bfloat16& l) {
    h = __float2bfloat16_rn(v);
    l = __float2bfloat16_rn(v - __bfloat162float(h));
}
__device__ __forceinline__ uint32_t pack2(__nv_bfloat16 a, __nv_bfloat16 b) {
    return (uint32_t)__bfloat16_as_ushort(a) | ((uint32_t)__bfloat16_as_ushort(b) << 16);
}

// ---------------- K_gfeat (+prep in blocks<64) ----------------
__global__ void __launch_bounds__(256) k_gfeat(const float* __restrict__ f,
                                               const float* __restrict__ w1,
                                               const float* __restrict__ w2,
                                               const float* __restrict__ w3) {
    __shared__ __align__(16) float w1t[64*68];
    __shared__ __align__(16) float fs[64*32];
    __shared__ __align__(16) float gs[32*68];
    int tid = threadIdx.x;
    int b  = blockIdx.x >> 6;
    int n0 = (blockIdx.x & 63) << 5;

    if (blockIdx.x < 64) {
        int i = blockIdx.x * 256 + tid;          // 0..16383
        { __nv_bfloat16 h, l; split_bf16(w2[i], h, l); g_w2h[i] = h; g_w2l[i] = l; }
        { __nv_bfloat16 h, l; split_bf16(w3[i], h, l); g_w3h[i] = h; g_w3l[i] = l; }
        if (i < Cc)   { g_s1[i]=0.0; g_ss1[i]=0.0; g_s3[i]=0.0; g_ss3[i]=0.0; }
        if (i < MIDm) { g_s2[i]=0.0; g_ss2[i]=0.0; }
    }

    for (int i = tid; i < 64*64; i += 256) {
        int c = i >> 6, cp = i & 63;
        w1t[cp*68 + c] = w1[c*67 + 3 + cp];
    }
    for (int i = tid; i < 64*32; i += 256) {
        int cp = i >> 5, nl = i & 31;
        fs[i] = f[(b*64 + cp)*2048 + n0 + nl];
    }
    __syncthreads();

    int nl = tid & 31, cg = tid >> 5;
    float acc[8];
    #pragma unroll
    for (int i = 0; i < 8; i++) acc[i] = 0.f;

    #pragma unroll 8
    for (int cp = 0; cp < 64; cp++) {
        float fv = fs[cp*32 + nl];
        float4 wa = *(const float4*)&w1t[cp*68 + cg*8];
        float4 wb = *(const float4*)&w1t[cp*68 + cg*8 + 4];
        acc[0] = fmaf(wa.x, fv, acc[0]);
        acc[1] = fmaf(wa.y, fv, acc[1]);
        acc[2] = fmaf(wa.z, fv, acc[2]);
        acc[3] = fmaf(wa.w, fv, acc[3]);
        acc[4] = fmaf(wb.x, fv, acc[4]);
        acc[5] = fmaf(wb.y, fv, acc[5]);
        acc[6] = fmaf(wb.z, fv, acc[6]);
        acc[7] = fmaf(wb.w, fv, acc[7]);
    }
    #pragma unroll
    for (int i = 0; i < 8; i++) gs[nl*68 + cg*8 + i] = acc[i];
    __syncthreads();
    for (int i = tid; i < 2048; i += 256) {
        int nn = i >> 6, c = i & 63;
        g_feat[(b*2048 + n0 + nn)*64 + c] = gs[nn*68 + c];
    }
}

// ---------------- K_ballq: 32 points per block ----------------
__global__ void __launch_bounds__(1024) k_ballq(const float* __restrict__ p) {
    __shared__ float px[2048], py[2048], pz[2048];
    __shared__ int   ob[32][16];
    int tid = threadIdx.x;
    int b  = blockIdx.x >> 6;
    int n0 = (blockIdx.x & 63) << 5;

    for (int i = tid; i < 2048; i += 1024) {
        const float* pp = p + (size_t)(b*2048 + i)*3;
        px[i] = pp[0]; py[i] = pp[1]; pz[i] = pp[2];
    }
    __syncthreads();

    int w = tid >> 5, lane = tid & 31;
    int n = n0 + w;
    float qx = px[n], qy = py[n], qz = pz[n];
    int cnt = 0;
    for (int j0 = 0; j0 < 2048; j0 += 32) {
        int j = j0 + lane;
        float dx = __fsub_rn(px[j], qx);
        float dy = __fsub_rn(py[j], qy);
        float dz = __fsub_rn(pz[j], qz);
        float d2 = __fadd_rn(__fadd_rn(__fmul_rn(dx,dx), __fmul_rn(dy,dy)), __fmul_rn(dz,dz));
        bool q = d2 < R2c;
        unsigned mask = __ballot_sync(0xffffffffu, q);
        if (mask) {
            int r = cnt + __popc(mask & ((1u << lane) - 1u));
            if (q && r < 16) ob[w][r] = j;
            cnt += __popc(mask);
            if (cnt >= 16) break;
        }
    }
    __syncwarp();
    if (cnt < 16) {
        int first = ob[w][0];
        if (lane >= cnt && lane < 16) ob[w][lane] = first;
        __syncwarp();
    }
    if (lane < 16) g_idx[(b*2048 + n)*16 + lane] = ob[w][lane];
}

// ---------------- K_agg ----------------
__global__ void __launch_bounds__(256) k_agg(const float* __restrict__ p,
                                             const float* __restrict__ w1) {
    __shared__ float ms[64*8];
    __shared__ float s1s[64], q1s[64];
    int tid = threadIdx.x;
    if (tid < 64) { s1s[tid] = 0.f; q1s[tid] = 0.f; }
    __syncthreads();

    int b  = blockIdx.x >> 8;
    int n0 = (blockIdx.x & 255) << 3;
    int w = tid >> 5, lane = tid & 31;
    int n = n0 + w;
    int c0 = lane * 2;

    float wx0 = w1[c0*67+0],     wy0 = w1[c0*67+1],     wz0 = w1[c0*67+2];
    float wx1 = w1[(c0+1)*67+0], wy1 = w1[(c0+1)*67+1], wz1 = w1[(c0+1)*67+2];
    const float* pc = p + (size_t)(b*2048 + n)*3;
    float cx = pc[0], cy = pc[1], cz = pc[2];
    int jr = g_idx[(b*2048 + n)*16 + (lane & 15)];

    float dxr = 0.f, dyr = 0.f, dzr = 0.f;
    if (lane < 16) {
        const float* pj = p + (size_t)(b*2048 + jr)*3;
        dxr = pj[0] - cx; dyr = pj[1] - cy; dzr = pj[2] - cz;
    }

    int js[16];
    #pragma unroll
    for (int k = 0; k < 16; k++) js[k] = __shfl_sync(0xffffffffu, jr, k);

    float2 gv[16];
    #pragma unroll
    for (int k = 0; k < 16; k++)
        gv[k] = __ldg((const float2*)(g_feat + (size_t)(b*2048 + js[k])*64 + c0));

    float mx0 = -3.402823466e38f, mx1 = -3.402823466e38f;
    float s0 = 0.f, q0 = 0.f, s1v = 0.f, q1v = 0.f;
    #pragma unroll
    for (int k = 0; k < 16; k++) {
        float dx = __shfl_sync(0xffffffffu, dxr, k);
        float dy = __shfl_sync(0xffffffffu, dyr, k);
        float dz = __shfl_sync(0xffffffffu, dzr, k);
        float v0 = fmaf(wx0, dx, fmaf(wy0, dy, fmaf(wz0, dz, gv[k].x)));
        float v1 = fmaf(wx1, dx, fmaf(wy1, dy, fmaf(wz1, dz, gv[k].y)));
        mx0 = fmaxf(mx0, v0); mx1 = fmaxf(mx1, v1);
        s0 += v0;  q0  = fmaf(v0, v0, q0);
        s1v += v1; q1v = fmaf(v1, v1, q1v);
    }
    ms[c0*8 + w]     = mx0;
    ms[(c0+1)*8 + w] = mx1;
    atomicAdd(&s1s[c0],   s0);  atomicAdd(&q1s[c0],   q0);
    atomicAdd(&s1s[c0+1], s1v); atomicAdd(&q1s[c0+1], q1v);
    __syncthreads();
    for (int i = tid; i < 512; i += 256) {
        int c = i >> 3, nl = i & 7;
        g_m[(b*64 + c)*2048 + n0 + nl] = ms[i];
    }
    if (tid < 64) {
        atomicAdd(&g_s1[tid],  (double)s1s[tid]);
        atomicAdd(&g_ss1[tid], (double)q1s[tid]);
    }
}

// ---------------- K_mlp1 (HMMA): y[c0..c0+128, n0..n0+128] = w2 @ relu(bn1(m)) ----------------
#define M1_AH 2048
#define M1_AL 20480
#define M1_BH 38912
#define M1_BL 56320
#define M1_SMEM 73728
#define LDA1 72
#define LDB1 136
__global__ void __launch_bounds__(256) k_mlp1(const float* __restrict__ g1,
                                              const float* __restrict__ b1) {
    extern __shared__ __align__(16) char smem[];
    uint32_t sb = smem_u32(smem);
    float* sc  = (float*)(smem);
    float* sh  = (float*)(smem + 256);
    float* s2s = (float*)(smem + 512);
    float* q2s = (float*)(smem + 1024);
    int tid = threadIdx.x, wid = tid >> 5, lane = tid & 31;
    int b  = blockIdx.x >> 5;
    int ct = (blockIdx.x >> 4) & 1;
    int nt = blockIdx.x & 15;
    int c0 = ct << 7, n0 = nt << 7;
    int c_w = (wid & 1) << 6, n_w = (wid >> 1) << 5;

    if (tid < 64) {
        double cnt = (double)(Bb*Nn*KK);
        double mu  = g_s1[tid] / cnt;
        double var = g_ss1[tid] / cnt - mu*mu;
        float s = g1[tid] * rsqrtf((float)var + EPSc);
        sc[tid] = s;
        sh[tid] = b1[tid] - (float)mu * s;
    }
    if (tid < 128) { s2s[tid] = 0.f; q2s[tid] = 0.f; }
    __syncthreads();

    // A fill: weights [128c x 64k] hi/lo via uint4
    for (int i = tid; i < 1024; i += 256) {
        int row = i >> 3, c8 = i & 7;
        *(uint4*)(smem + M1_AH + row*(LDA1*2) + c8*16) =
            ((const uint4*)(g_w2h + (size_t)(c0 + row)*64))[c8];
        *(uint4*)(smem + M1_AL + row*(LDA1*2) + c8*16) =
            ((const uint4*)(g_w2l + (size_t)(c0 + row)*64))[c8];
    }
    // B fill (packed pairs): h = relu(bn1(m)) split, [64k x 128n]
    for (int i = tid; i < 4096; i += 256) {
        int k = i >> 6, np = i & 63;
        float2 v = *(const float2*)&g_m[(b*64 + k)*2048 + n0 + np*2];
        float sck = sc[k], shk = sh[k];
        float va = fmaxf(0.f, fmaf(v.x, sck, shk));
        float vb = fmaxf(0.f, fmaf(v.y, sck, shk));
        __nv_bfloat16 ha, la, hb, lb;
        split_bf16(va, ha, la);
        split_bf16(vb, hb, lb);
        *(uint32_t*)(smem + M1_BH + k*(LDB1*2) + np*4) = pack2(ha, hb);
        *(uint32_t*)(smem + M1_BL + k*(LDB1*2) + np*4) = pack2(la, lb);
    }
    __syncthreads();

    float acc[4][4][4];
    #pragma unroll
    for (int i = 0; i < 4; i++)
        #pragma unroll
        for (int j = 0; j < 4; j++)
            #pragma unroll
            for (int r = 0; r < 4; r++) acc[i][j][r] = 0.f;

    uint32_t arow = lane & 15, acol = (lane >> 4) << 3;
    uint32_t brow = lane & 15;
    #pragma unroll
    for (int ks = 0; ks < 4; ks++) {
        uint32_t bh[4][2], bl[4][2];
        #pragma unroll
        for (int ntl = 0; ntl < 4; ntl++) {
            uint32_t baddr = (ks*16 + brow)*(LDB1*2) + (n_w + ntl*8)*2;
            ldmB(bh[ntl], sb + M1_BH + baddr);
            ldmB(bl[ntl], sb + M1_BL + baddr);
        }
        #pragma unroll
        for (int mt = 0; mt < 4; mt++) {
            uint32_t aaddr = (c_w + mt*16 + arow)*(LDA1*2) + (ks*16 + acol)*2;
            uint32_t ah[4], al[4];
            ldmA(ah, sb + M1_AH + aaddr);
            ldmA(al, sb + M1_AL + aaddr);
            #pragma unroll
            for (int ntl = 0; ntl < 4; ntl++) {
                mma16816(acc[mt][ntl], ah, bh[ntl]);
                mma16816(acc[mt][ntl], ah, bl[ntl]);
                mma16816(acc[mt][ntl], al, bh[ntl]);
            }
        }
    }

    int g = lane >> 2, tcol = (lane & 3) * 2;
    #pragma unroll
    for (int mt = 0; mt < 4; mt++) {
        int r0 = c_w + mt*16 + g, r1 = r0 + 8;
        float s0 = 0.f, q0 = 0.f, s1v = 0.f, q1v = 0.f;
        #pragma unroll
        for (int ntl = 0; ntl < 4; ntl++) {
            float d0 = acc[mt][ntl][0], d1 = acc[mt][ntl][1];
            float d2 = acc[mt][ntl][2], d3 = acc[mt][ntl][3];
            int col = n_w + ntl*8 + tcol;
            *(float2*)&g_y[(size_t)(b*256 + c0 + r0)*2048 + n0 + col] = make_float2(d0, d1);
            *(float2*)&g_y[(size_t)(b*256 + c0 + r1)*2048 + n0 + col] = make_float2(d2, d3);
            s0 += d0 + d1; q0 = fmaf(d0, d0, fmaf(d1, d1, q0));
            s1v += d2 + d3; q1v = fmaf(d2, d2, fmaf(d3, d3, q1v));
        }
        atomicAdd(&s2s[r0], s0);  atomicAdd(&q2s[r0], q0);
        atomicAdd(&s2s[r1], s1v); atomicAdd(&q2s[r1], q1v);
    }
    __syncthreads();
    if (tid < 128) {
        atomicAdd(&g_s2[c0 + tid],  (double)s2s[tid]);
        atomicAdd(&g_ss2[c0 + tid], (double)q2s[tid]);
    }
}

// ---------------- K_mlp2 (HMMA): z[64c, n0..n0+64] = w3 @ relu(bn2(y)) ----------------
// block = 64c x 64n, 8 warps of 16c x 32n. grid = 8b x 32nt = 256.
// smem: sc@0[1024] sh@1024[1024] s3s@2048[256] q3s@2304[256]
//   A_hi@2560 (64x72 bf16 = 9216)  A_lo@11776  B_hi@20992 (64x72 = 9216)  B_lo@30208
#define M2_AH 2560
#define M2_AL 11776
#define M2_BH 20992
#define M2_BL 30208
#define M2_SMEM 39424
#define LDA2 72
#define LDB2 72
__global__ void __launch_bounds__(256) k_mlp2(const float* __restrict__ g2,
                                              const float* __restrict__ b2) {
    extern __shared__ __align__(16) char smem[];
    uint32_t sb = smem_u32(smem);
    float* sc  = (float*)(smem);
    float* sh  = (float*)(smem + 1024);
    float* s3s = (float*)(smem + 2048);
    float* q3s = (float*)(smem + 2304);
    int tid = threadIdx.x, wid = tid >> 5, lane = tid & 31;
    int b  = blockIdx.x >> 5;
    int n0 = (blockIdx.x & 31) << 6;
    int c_w = (wid & 3) << 4;   // 0,16,32,48
    int n_w = (wid >> 2) << 5;  // 0,32

    {
        double cnt = (double)(Bb*Nn);
        double mu  = g_s2[tid] / cnt;
        double var = g_ss2[tid] / cnt - mu*mu;
        float s = g2[tid] * rsqrtf((float)var + EPSc);
        sc[tid] = s;
        sh[tid] = b2[tid] - (float)mu * s;
    }
    if (tid < 64) { s3s[tid] = 0.f; q3s[tid] = 0.f; }
    __syncthreads();

    float acc[4][4];
    #pragma unroll
    for (int i = 0; i < 4; i++)
        #pragma unroll
        for (int r = 0; r < 4; r++) acc[i][r] = 0.f;

    uint32_t arow = lane & 15, acol = (lane >> 4) << 3;
    uint32_t brow = lane & 15;

    for (int q = 0; q < 4; q++) {           // K chunks of 64
        int k0 = q << 6;
        // A fill: w3 [64c x 64k slice]
        for (int i = tid; i < 512; i += 256) {
            int row = i >> 3, c8 = i & 7;
            *(uint4*)(smem + M2_AH + row*(LDA2*2) + c8*16) =
                ((const uint4*)(g_w3h + (size_t)row*256 + k0))[c8];
            *(uint4*)(smem + M2_AL + row*(LDA2*2) + c8*16) =
                ((const uint4*)(g_w3l + (size_t)row*256 + k0))[c8];
        }
        // B fill (packed pairs): u = relu(bn2(y)) split, [64k x 64n]
        for (int i = tid; i < 2048; i += 256) {
            int k = i >> 5, np = i & 31;
            int ch = k0 + k;
            float2 v = *(const float2*)&g_y[(size_t)(b*256 + ch)*2048 + n0 + np*2];
            float sck = sc[ch], shk = sh[ch];
            float va = fmaxf(0.f, fmaf(v.x, sck, shk));
            float vb = fmaxf(0.f, fmaf(v.y, sck, shk));
            __nv_bfloat16 ha, la, hb, lb;
            split_bf16(va, ha, la);
            split_bf16(vb, hb, lb);
            *(uint32_t*)(smem + M2_BH + k*(LDB2*2) + np*4) = pack2(ha, hb);
            *(uint32_t*)(smem + M2_BL + k*(LDB2*2) + np*4) = pack2(la, lb);
        }
        __syncthreads();

        #pragma unroll
        for (int ks = 0; ks < 4; ks++) {
            uint32_t bh[4][2], bl[4][2];
            #pragma unroll
            for (int ntl = 0; ntl < 4; ntl++) {
                uint32_t baddr = (ks*16 + brow)*(LDB2*2) + (n_w + ntl*8)*2;
                ldmB(bh[ntl], sb + M2_BH + baddr);
                ldmB(bl[ntl], sb + M2_BL + baddr);
            }
            uint32_t aaddr = (c_w + arow)*(LDA2*2) + (ks*16 + acol)*2;
            uint32_t ah[4], al[4];
            ldmA(ah, sb + M2_AH + aaddr);
            ldmA(al, sb + M2_AL + aaddr);
            #pragma unroll
            for (int ntl = 0; ntl < 4; ntl++) {
                mma16816(acc[ntl], ah, bh[ntl]);
                mma16816(acc[ntl], ah, bl[ntl]);
                mma16816(acc[ntl], al, bh[ntl]);
            }
        }
        __syncthreads();
    }

    int g = lane >> 2, tcol = (lane & 3) * 2;
    {
        int r0 = c_w + g, r1 = r0 + 8;
        float s0 = 0.f, q0 = 0.f, s1v = 0.f, q1v = 0.f;
        #pragma unroll
        for (int ntl = 0; ntl < 4; ntl++) {
            float d0 = acc[ntl][0], d1 = acc[ntl][1];
            float d2 = acc[ntl][2], d3 = acc[ntl][3];
            int col = n_w + ntl*8 + tcol;
            *(float2*)&g_z[(size_t)(b*64 + r0)*2048 + n0 + col] = make_float2(d0, d1);
            *(float2*)&g_z[(size_t)(b*64 + r1)*2048 + n0 + col] = make_float2(d2, d3);
            s0 += d0 + d1; q0 = fmaf(d0, d0, fmaf(d1, d1, q0));
            s1v += d2 + d3; q1v = fmaf(d2, d2, fmaf(d3, d3, q1v));
        }
        atomicAdd(&s3s[r0], s0);  atomicAdd(&q3s[r0], q0);
        atomicAdd(&s3s[r1], s1v); atomicAdd(&q3s[r1], q1v);
    }
    __syncthreads();
    if (tid < 64) {
        atomicAdd(&g_s3[tid],  (double)s3s[tid]);
        atomicAdd(&g_ss3[tid], (double)q3s[tid]);
    }
}

// ---------------- K_out: relu(bn3(z) + f) ----------------
__global__ void __launch_bounds__(256) k_out(const float* __restrict__ f,
                                             const float* __restrict__ g3,
                                             const float* __restrict__ b3,
                                             float* __restrict__ out) {
    __shared__ float sc[64], sh[64];
    int tid = threadIdx.x;
    if (tid < 64) {
        double cnt = (double)(Bb*Nn);
        double mu  = g_s3[tid] / cnt;
        double var = g_ss3[tid] / cnt - mu*mu;
        float s = g3[tid] * rsqrtf((float)var + EPSc);
        sc[tid] = s;
        sh[tid] = b3[tid] - (float)mu * s;
    }
    __syncthreads();
    int i = blockIdx.x * 256 + tid;
    int base = i * 4;
    int c = (base >> 11) & 63;
    float4 z  = *(const float4*)&g_z[base];
    float4 fv = *(const float4*)&f[base];
    float4 o;
    o.x = fmaxf(0.f, fmaf(z.x, sc[c], sh[c]) + fv.x);
    o.y = fmaxf(0.f, fmaf(z.y, sc[c], sh[c]) + fv.y);
    o.z = fmaxf(0.f, fmaf(z.z, sc[c], sh[c]) + fv.z);
    o.w = fmaxf(0.f, fmaf(z.w, sc[c], sh[c]) + fv.w);
    *(float4*)&out[base] = o;
}

// ---------------- launch ----------------
extern "C" void kernel_launch(void* const* d_in, const int* in_sizes, int n_in,
                              void* d_out, int out_size) {
    const float* p  = (const float*)d_in[0];
    const float* f  = (const float*)d_in[1];
    const float* w1 = (const float*)d_in[2];
    const float* g1 = (const float*)d_in[3];
    const float* b1 = (const float*)d_in[4];
    const float* w2 = (const float*)d_in[5];
    const float* g2 = (const float*)d_in[6];
    const float* b2 = (const float*)d_in[7];
    const float* w3 = (const float*)d_in[8];
    const float* g3 = (const float*)d_in[9];
    const float* b3 = (const float*)d_in[10];
    float* out = (float*)d_out;

    cudaFuncSetAttribute(k_mlp1, cudaFuncAttributeMaxDynamicSharedMemorySize, M1_SMEM);
    cudaFuncSetAttribute(k_mlp2, cudaFuncAttributeMaxDynamicSharedMemorySize, M2_SMEM);

    k_gfeat<<<512,  256>>>(f, w1, w2, w3);
    k_ballq<<<512, 1024>>>(p);
    k_agg  <<<2048, 256>>>(p, w1);
    k_mlp1 <<<256,  256, M1_SMEM>>>(g1, b1);
    k_mlp2 <<<256,  256, M2_SMEM>>>(g2, b2);
    k_out  <<<1024, 256>>>(f, g3, b3, out);
}

// round 9
// speedup vs baseline: 2.0749x; 1.0569x over previous
#include <cuda_runtime.h>
#include <cuda_bf16.h>
#include <cstdint>

#define Bb   8
#define Nn   2048
#define Cc   64
#define MIDm 256
#define KK   16
#define R2c  0.0225f
#define EPSc 1e-5f

// ---------------- scratch (device globals, no allocation) ----------------
__device__ __align__(16) int    g_idx[Bb*Nn*KK];      // [b][n][16]
__device__ __align__(16) float  g_feat[Bb*Nn*Cc];     // [b][n][c]  = w1[:,3:]@f
__device__ __align__(16) float  g_m[Bb*Cc*Nn];        // [b][c][n]  = max_k x
__device__ __align__(16) float  g_y[Bb*MIDm*Nn];      // [b][c][n]
__device__ __align__(16) float  g_z[Bb*Cc*Nn];        // [b][c][n]
// split-bf16 weights (same layout as source, no transpose needed)
__device__ __align__(16) __nv_bfloat16 g_w2h[MIDm*Cc], g_w2l[MIDm*Cc];   // [o=256][k=64]
__device__ __align__(16) __nv_bfloat16 g_w3h[Cc*MIDm], g_w3l[Cc*MIDm];   // [c=64][k=256]
__device__ double g_s1[Cc],   g_ss1[Cc];
__device__ double g_s2[MIDm], g_ss2[MIDm];
__device__ double g_s3[Cc],   g_ss3[Cc];

// ---------------- mma/ldmatrix helpers ----------------
__device__ __forceinline__ uint32_t smem_u32(const void* p) {
    uint32_t r;
    asm("{ .reg .u64 t; cvta.to.shared.u64 t, %1; cvt.u32.u64 %0, t; }" : "=r"(r) : "l"(p));
    return r;
}
__device__ __forceinline__ void ldmA(uint32_t* a, uint32_t addr) {   // x4 non-trans
    asm volatile("ldmatrix.sync.aligned.m8n8.x4.shared.b16 {%0,%1,%2,%3}, [%4];"
                 : "=r"(a[0]), "=r"(a[1]), "=r"(a[2]), "=r"(a[3]) : "r"(addr));
}
__device__ __forceinline__ void ldmB(uint32_t* b2, uint32_t addr) {  // x2 trans
    asm volatile("ldmatrix.sync.aligned.m8n8.x2.trans.shared.b16 {%0,%1}, [%2];"
                 : "=r"(b2[0]), "=r"(b2[1]) : "r"(addr));
}
__device__ __forceinline__ void mma16816(float* d, const uint32_t* a, const uint32_t* b2) {
    asm volatile(
        "mma.sync.aligned.m16n8k16.row.col.f32.bf16.bf16.f32 "
        "{%0,%1,%2,%3}, {%4,%5,%6,%7}, {%8,%9}, {%0,%1,%2,%3};"
        : "+f"(d[0]), "+f"(d[1]), "+f"(d[2]), "+f"(d[3])
        : "r"(a[0]), "r"(a[1]), "r"(a[2]), "r"(a[3]), "r"(b2[0]), "r"(b2[1]));
}
__device__ __forceinline__ void split_bf16(float v, __nv_bfloat16& h, __nv_bfloat16& l) {
    h = __float2bfloat16_rn(v);
    l = __float2bfloat16_rn(v - __bfloat162float(h));
}
__device__ __forceinline__ uint32_t pack2(__nv_bfloat16 a, __nv_bfloat16 b) {
    return (uint32_t)__bfloat16_as_ushort(a) | ((uint32_t)__bfloat16_as_ushort(b) << 16);
}

// ---------------- K_gfeat (+prep in blocks<64) ----------------
__global__ void __launch_bounds__(256) k_gfeat(const float* __restrict__ f,
                                               const float* __restrict__ w1,
                                               const float* __restrict__ w2,
                                               const float* __restrict__ w3) {
    __shared__ __align__(16) float w1t[64*68];
    __shared__ __align__(16) float fs[64*32];
    __shared__ __align__(16) float gs[32*68];
    int tid = threadIdx.x;
    int b  = blockIdx.x >> 6;
    int n0 = (blockIdx.x & 63) << 5;

    if (blockIdx.x < 64) {
        int i = blockIdx.x * 256 + tid;          // 0..16383
        { __nv_bfloat16 h, l; split_bf16(w2[i], h, l); g_w2h[i] = h; g_w2l[i] = l; }
        { __nv_bfloat16 h, l; split_bf16(w3[i], h, l); g_w3h[i] = h; g_w3l[i] = l; }
        if (i < Cc)   { g_s1[i]=0.0; g_ss1[i]=0.0; g_s3[i]=0.0; g_ss3[i]=0.0; }
        if (i < MIDm) { g_s2[i]=0.0; g_ss2[i]=0.0; }
    }

    for (int i = tid; i < 64*64; i += 256) {
        int c = i >> 6, cp = i & 63;
        w1t[cp*68 + c] = w1[c*67 + 3 + cp];
    }
    for (int i = tid; i < 64*32; i += 256) {
        int cp = i >> 5, nl = i & 31;
        fs[i] = f[(b*64 + cp)*2048 + n0 + nl];
    }
    __syncthreads();

    int nl = tid & 31, cg = tid >> 5;
    float acc[8];
    #pragma unroll
    for (int i = 0; i < 8; i++) acc[i] = 0.f;

    #pragma unroll 8
    for (int cp = 0; cp < 64; cp++) {
        float fv = fs[cp*32 + nl];
        float4 wa = *(const float4*)&w1t[cp*68 + cg*8];
        float4 wb = *(const float4*)&w1t[cp*68 + cg*8 + 4];
        acc[0] = fmaf(wa.x, fv, acc[0]);
        acc[1] = fmaf(wa.y, fv, acc[1]);
        acc[2] = fmaf(wa.z, fv, acc[2]);
        acc[3] = fmaf(wa.w, fv, acc[3]);
        acc[4] = fmaf(wb.x, fv, acc[4]);
        acc[5] = fmaf(wb.y, fv, acc[5]);
        acc[6] = fmaf(wb.z, fv, acc[6]);
        acc[7] = fmaf(wb.w, fv, acc[7]);
    }
    #pragma unroll
    for (int i = 0; i < 8; i++) gs[nl*68 + cg*8 + i] = acc[i];
    __syncthreads();
    for (int i = tid; i < 2048; i += 256) {
        int nn = i >> 6, c = i & 63;
        g_feat[(b*2048 + n0 + nn)*64 + c] = gs[nn*68 + c];
    }
}

// ---------------- K_ballq: 32 points per block ----------------
__global__ void __launch_bounds__(1024) k_ballq(const float* __restrict__ p) {
    __shared__ float px[2048], py[2048], pz[2048];
    __shared__ int   ob[32][16];
    int tid = threadIdx.x;
    int b  = blockIdx.x >> 6;
    int n0 = (blockIdx.x & 63) << 5;

    for (int i = tid; i < 2048; i += 1024) {
        const float* pp = p + (size_t)(b*2048 + i)*3;
        px[i] = pp[0]; py[i] = pp[1]; pz[i] = pp[2];
    }
    __syncthreads();

    int w = tid >> 5, lane = tid & 31;
    int n = n0 + w;
    float qx = px[n], qy = py[n], qz = pz[n];
    int cnt = 0;
    for (int j0 = 0; j0 < 2048; j0 += 32) {
        int j = j0 + lane;
        float dx = __fsub_rn(px[j], qx);
        float dy = __fsub_rn(py[j], qy);
        float dz = __fsub_rn(pz[j], qz);
        float d2 = __fadd_rn(__fadd_rn(__fmul_rn(dx,dx), __fmul_rn(dy,dy)), __fmul_rn(dz,dz));
        bool q = d2 < R2c;
        unsigned mask = __ballot_sync(0xffffffffu, q);
        if (mask) {
            int r = cnt + __popc(mask & ((1u << lane) - 1u));
            if (q && r < 16) ob[w][r] = j;
            cnt += __popc(mask);
            if (cnt >= 16) break;
        }
    }
    __syncwarp();
    if (cnt < 16) {
        int first = ob[w][0];
        if (lane >= cnt && lane < 16) ob[w][lane] = first;
        __syncwarp();
    }
    if (lane < 16) g_idx[(b*2048 + n)*16 + lane] = ob[w][lane];
}

// ---------------- K_agg ----------------
__global__ void __launch_bounds__(256) k_agg(const float* __restrict__ p,
                                             const float* __restrict__ w1) {
    __shared__ float ms[64*8];
    __shared__ float s1s[64], q1s[64];
    int tid = threadIdx.x;
    if (tid < 64) { s1s[tid] = 0.f; q1s[tid] = 0.f; }
    __syncthreads();

    int b  = blockIdx.x >> 8;
    int n0 = (blockIdx.x & 255) << 3;
    int w = tid >> 5, lane = tid & 31;
    int n = n0 + w;
    int c0 = lane * 2;

    float wx0 = w1[c0*67+0],     wy0 = w1[c0*67+1],     wz0 = w1[c0*67+2];
    float wx1 = w1[(c0+1)*67+0], wy1 = w1[(c0+1)*67+1], wz1 = w1[(c0+1)*67+2];
    const float* pc = p + (size_t)(b*2048 + n)*3;
    float cx = pc[0], cy = pc[1], cz = pc[2];
    int jr = g_idx[(b*2048 + n)*16 + (lane & 15)];

    float dxr = 0.f, dyr = 0.f, dzr = 0.f;
    if (lane < 16) {
        const float* pj = p + (size_t)(b*2048 + jr)*3;
        dxr = pj[0] - cx; dyr = pj[1] - cy; dzr = pj[2] - cz;
    }

    int js[16];
    #pragma unroll
    for (int k = 0; k < 16; k++) js[k] = __shfl_sync(0xffffffffu, jr, k);

    float2 gv[16];
    #pragma unroll
    for (int k = 0; k < 16; k++)
        gv[k] = __ldg((const float2*)(g_feat + (size_t)(b*2048 + js[k])*64 + c0));

    float mx0 = -3.402823466e38f, mx1 = -3.402823466e38f;
    float s0 = 0.f, q0 = 0.f, s1v = 0.f, q1v = 0.f;
    #pragma unroll
    for (int k = 0; k < 16; k++) {
        float dx = __shfl_sync(0xffffffffu, dxr, k);
        float dy = __shfl_sync(0xffffffffu, dyr, k);
        float dz = __shfl_sync(0xffffffffu, dzr, k);
        float v0 = fmaf(wx0, dx, fmaf(wy0, dy, fmaf(wz0, dz, gv[k].x)));
        float v1 = fmaf(wx1, dx, fmaf(wy1, dy, fmaf(wz1, dz, gv[k].y)));
        mx0 = fmaxf(mx0, v0); mx1 = fmaxf(mx1, v1);
        s0 += v0;  q0  = fmaf(v0, v0, q0);
        s1v += v1; q1v = fmaf(v1, v1, q1v);
    }
    ms[c0*8 + w]     = mx0;
    ms[(c0+1)*8 + w] = mx1;
    atomicAdd(&s1s[c0],   s0);  atomicAdd(&q1s[c0],   q0);
    atomicAdd(&s1s[c0+1], s1v); atomicAdd(&q1s[c0+1], q1v);
    __syncthreads();
    for (int i = tid; i < 512; i += 256) {
        int c = i >> 3, nl = i & 7;
        g_m[(b*64 + c)*2048 + n0 + nl] = ms[i];
    }
    if (tid < 64) {
        atomicAdd(&g_s1[tid],  (double)s1s[tid]);
        atomicAdd(&g_ss1[tid], (double)q1s[tid]);
    }
}

// ---------------- K_mlp1 (HMMA): y[c0..c0+128, n0..n0+64] = w2 @ relu(bn1(m)) ----------------
// block = 128c x 64n, 8 warps of 32c x 32n. grid = 8b x 2ct x 32nt = 512.
// smem: sc@0[256] sh@256[256] s2s@512[512] q2s@1024[512]
//   A_hi@2048 (128x72 bf16 = 18432)  A_lo@20480  B_hi@38912 (64x72 = 9216)  B_lo@48128
#define M1_AH 2048
#define M1_AL 20480
#define M1_BH 38912
#define M1_BL 48128
#define M1_SMEM 57344
#define LDA1 72
#define LDB1 72
__global__ void __launch_bounds__(256) k_mlp1(const float* __restrict__ g1,
                                              const float* __restrict__ b1) {
    extern __shared__ __align__(16) char smem[];
    uint32_t sb = smem_u32(smem);
    float* sc  = (float*)(smem);
    float* sh  = (float*)(smem + 256);
    float* s2s = (float*)(smem + 512);
    float* q2s = (float*)(smem + 1024);
    int tid = threadIdx.x, wid = tid >> 5, lane = tid & 31;
    int b  = blockIdx.x >> 6;
    int ct = (blockIdx.x >> 5) & 1;
    int nt = blockIdx.x & 31;
    int c0 = ct << 7, n0 = nt << 6;
    int c_w = (wid & 3) << 5, n_w = (wid >> 2) << 5;

    // prefetch A (weights) and B (g_m) while computing bn params
    uint4 pa_h[4], pa_l[4];
    #pragma unroll
    for (int j = 0; j < 4; j++) {
        int i = tid + j*256;
        int row = i >> 3, c8 = i & 7;
        pa_h[j] = ((const uint4*)(g_w2h + (size_t)(c0 + row)*64))[c8];
        pa_l[j] = ((const uint4*)(g_w2l + (size_t)(c0 + row)*64))[c8];
    }
    float2 pb[8];
    #pragma unroll
    for (int j = 0; j < 8; j++) {
        int i = tid + j*256;
        int k = i >> 5, np = i & 31;
        pb[j] = *(const float2*)&g_m[(b*64 + k)*2048 + n0 + np*2];
    }

    if (tid < 64) {
        double cnt = (double)(Bb*Nn*KK);
        double mu  = g_s1[tid] / cnt;
        double var = g_ss1[tid] / cnt - mu*mu;
        float s = g1[tid] * rsqrtf((float)var + EPSc);
        sc[tid] = s;
        sh[tid] = b1[tid] - (float)mu * s;
    }
    if (tid < 128) { s2s[tid] = 0.f; q2s[tid] = 0.f; }
    __syncthreads();

    #pragma unroll
    for (int j = 0; j < 4; j++) {
        int i = tid + j*256;
        int row = i >> 3, c8 = i & 7;
        *(uint4*)(smem + M1_AH + row*(LDA1*2) + c8*16) = pa_h[j];
        *(uint4*)(smem + M1_AL + row*(LDA1*2) + c8*16) = pa_l[j];
    }
    #pragma unroll
    for (int j = 0; j < 8; j++) {
        int i = tid + j*256;
        int k = i >> 5, np = i & 31;
        float sck = sc[k], shk = sh[k];
        float va = fmaxf(0.f, fmaf(pb[j].x, sck, shk));
        float vb = fmaxf(0.f, fmaf(pb[j].y, sck, shk));
        __nv_bfloat16 ha, la, hb, lb;
        split_bf16(va, ha, la);
        split_bf16(vb, hb, lb);
        *(uint32_t*)(smem + M1_BH + k*(LDB1*2) + np*4) = pack2(ha, hb);
        *(uint32_t*)(smem + M1_BL + k*(LDB1*2) + np*4) = pack2(la, lb);
    }
    __syncthreads();

    float acc[2][4][4];
    #pragma unroll
    for (int i = 0; i < 2; i++)
        #pragma unroll
        for (int j = 0; j < 4; j++)
            #pragma unroll
            for (int r = 0; r < 4; r++) acc[i][j][r] = 0.f;

    uint32_t arow = lane & 15, acol = (lane >> 4) << 3;
    uint32_t brow = lane & 15;
    #pragma unroll
    for (int ks = 0; ks < 4; ks++) {
        uint32_t bh[4][2], bl[4][2];
        #pragma unroll
        for (int ntl = 0; ntl < 4; ntl++) {
            uint32_t baddr = (ks*16 + brow)*(LDB1*2) + (n_w + ntl*8)*2;
            ldmB(bh[ntl], sb + M1_BH + baddr);
            ldmB(bl[ntl], sb + M1_BL + baddr);
        }
        #pragma unroll
        for (int mt = 0; mt < 2; mt++) {
            uint32_t aaddr = (c_w + mt*16 + arow)*(LDA1*2) + (ks*16 + acol)*2;
            uint32_t ah[4], al[4];
            ldmA(ah, sb + M1_AH + aaddr);
            ldmA(al, sb + M1_AL + aaddr);
            #pragma unroll
            for (int ntl = 0; ntl < 4; ntl++) {
                mma16816(acc[mt][ntl], ah, bh[ntl]);
                mma16816(acc[mt][ntl], ah, bl[ntl]);
                mma16816(acc[mt][ntl], al, bh[ntl]);
            }
        }
    }

    int g = lane >> 2, tcol = (lane & 3) * 2;
    #pragma unroll
    for (int mt = 0; mt < 2; mt++) {
        int r0 = c_w + mt*16 + g, r1 = r0 + 8;
        float s0 = 0.f, q0 = 0.f, s1v = 0.f, q1v = 0.f;
        #pragma unroll
        for (int ntl = 0; ntl < 4; ntl++) {
            float d0 = acc[mt][ntl][0], d1 = acc[mt][ntl][1];
            float d2 = acc[mt][ntl][2], d3 = acc[mt][ntl][3];
            int col = n_w + ntl*8 + tcol;
            *(float2*)&g_y[(size_t)(b*256 + c0 + r0)*2048 + n0 + col] = make_float2(d0, d1);
            *(float2*)&g_y[(size_t)(b*256 + c0 + r1)*2048 + n0 + col] = make_float2(d2, d3);
            s0 += d0 + d1; q0 = fmaf(d0, d0, fmaf(d1, d1, q0));
            s1v += d2 + d3; q1v = fmaf(d2, d2, fmaf(d3, d3, q1v));
        }
        atomicAdd(&s2s[r0], s0);  atomicAdd(&q2s[r0], q0);
        atomicAdd(&s2s[r1], s1v); atomicAdd(&q2s[r1], q1v);
    }
    __syncthreads();
    if (tid < 128) {
        atomicAdd(&g_s2[c0 + tid],  (double)s2s[tid]);
        atomicAdd(&g_ss2[c0 + tid], (double)q2s[tid]);
    }
}

// ---------------- K_mlp2 (HMMA): z[64c, n0..n0+64] = w3 @ relu(bn2(y)) ----------------
// block = 64c x 64n, 8 warps of 16c x 32n. grid = 8b x 32nt = 256.
#define M2_AH 2560
#define M2_AL 11776
#define M2_BH 20992
#define M2_BL 30208
#define M2_SMEM 39424
#define LDA2 72
#define LDB2 72
__global__ void __launch_bounds__(256) k_mlp2(const float* __restrict__ g2,
                                              const float* __restrict__ b2) {
    extern __shared__ __align__(16) char smem[];
    uint32_t sb = smem_u32(smem);
    float* sc  = (float*)(smem);
    float* sh  = (float*)(smem + 1024);
    float* s3s = (float*)(smem + 2048);
    float* q3s = (float*)(smem + 2304);
    int tid = threadIdx.x, wid = tid >> 5, lane = tid & 31;
    int b  = blockIdx.x >> 5;
    int n0 = (blockIdx.x & 31) << 6;
    int c_w = (wid & 3) << 4;   // 0,16,32,48
    int n_w = (wid >> 2) << 5;  // 0,32

    {
        double cnt = (double)(Bb*Nn);
        double mu  = g_s2[tid] / cnt;
        double var = g_ss2[tid] / cnt - mu*mu;
        float s = g2[tid] * rsqrtf((float)var + EPSc);
        sc[tid] = s;
        sh[tid] = b2[tid] - (float)mu * s;
    }
    if (tid < 64) { s3s[tid] = 0.f; q3s[tid] = 0.f; }
    __syncthreads();

    float acc[4][4];
    #pragma unroll
    for (int i = 0; i < 4; i++)
        #pragma unroll
        for (int r = 0; r < 4; r++) acc[i][r] = 0.f;

    uint32_t arow = lane & 15, acol = (lane >> 4) << 3;
    uint32_t brow = lane & 15;

    for (int q = 0; q < 4; q++) {           // K chunks of 64
        int k0 = q << 6;
        // prefetch chunk
        uint4 pa_h[2], pa_l[2];
        #pragma unroll
        for (int j = 0; j < 2; j++) {
            int i = tid + j*256;
            int row = i >> 3, c8 = i & 7;
            pa_h[j] = ((const uint4*)(g_w3h + (size_t)row*256 + k0))[c8];
            pa_l[j] = ((const uint4*)(g_w3l + (size_t)row*256 + k0))[c8];
        }
        float2 pbv[8];
        #pragma unroll
        for (int j = 0; j < 8; j++) {
            int i = tid + j*256;
            int k = i >> 5, np = i & 31;
            pbv[j] = *(const float2*)&g_y[(size_t)(b*256 + k0 + k)*2048 + n0 + np*2];
        }
        #pragma unroll
        for (int j = 0; j < 2; j++) {
            int i = tid + j*256;
            int row = i >> 3, c8 = i & 7;
            *(uint4*)(smem + M2_AH + row*(LDA2*2) + c8*16) = pa_h[j];
            *(uint4*)(smem + M2_AL + row*(LDA2*2) + c8*16) = pa_l[j];
        }
        #pragma unroll
        for (int j = 0; j < 8; j++) {
            int i = tid + j*256;
            int k = i >> 5, np = i & 31;
            int ch = k0 + k;
            float sck = sc[ch], shk = sh[ch];
            float va = fmaxf(0.f, fmaf(pbv[j].x, sck, shk));
            float vb = fmaxf(0.f, fmaf(pbv[j].y, sck, shk));
            __nv_bfloat16 ha, la, hb, lb;
            split_bf16(va, ha, la);
            split_bf16(vb, hb, lb);
            *(uint32_t*)(smem + M2_BH + k*(LDB2*2) + np*4) = pack2(ha, hb);
            *(uint32_t*)(smem + M2_BL + k*(LDB2*2) + np*4) = pack2(la, lb);
        }
        __syncthreads();

        #pragma unroll
        for (int ks = 0; ks < 4; ks++) {
            uint32_t bh[4][2], bl[4][2];
            #pragma unroll
            for (int ntl = 0; ntl < 4; ntl++) {
                uint32_t baddr = (ks*16 + brow)*(LDB2*2) + (n_w + ntl*8)*2;
                ldmB(bh[ntl], sb + M2_BH + baddr);
                ldmB(bl[ntl], sb + M2_BL + baddr);
            }
            uint32_t aaddr = (c_w + arow)*(LDA2*2) + (ks*16 + acol)*2;
            uint32_t ah[4], al[4];
            ldmA(ah, sb + M2_AH + aaddr);
            ldmA(al, sb + M2_AL + aaddr);
            #pragma unroll
            for (int ntl = 0; ntl < 4; ntl++) {
                mma16816(acc[ntl], ah, bh[ntl]);
                mma16816(acc[ntl], ah, bl[ntl]);
                mma16816(acc[ntl], al, bh[ntl]);
            }
        }
        __syncthreads();
    }

    int g = lane >> 2, tcol = (lane & 3) * 2;
    {
        int r0 = c_w + g, r1 = r0 + 8;
        float s0 = 0.f, q0 = 0.f, s1v = 0.f, q1v = 0.f;
        #pragma unroll
        for (int ntl = 0; ntl < 4; ntl++) {
            float d0 = acc[ntl][0], d1 = acc[ntl][1];
            float d2 = acc[ntl][2], d3 = acc[ntl][3];
            int col = n_w + ntl*8 + tcol;
            *(float2*)&g_z[(size_t)(b*64 + r0)*2048 + n0 + col] = make_float2(d0, d1);
            *(float2*)&g_z[(size_t)(b*64 + r1)*2048 + n0 + col] = make_float2(d2, d3);
            s0 += d0 + d1; q0 = fmaf(d0, d0, fmaf(d1, d1, q0));
            s1v += d2 + d3; q1v = fmaf(d2, d2, fmaf(d3, d3, q1v));
        }
        atomicAdd(&s3s[r0], s0);  atomicAdd(&q3s[r0], q0);
        atomicAdd(&s3s[r1], s1v); atomicAdd(&q3s[r1], q1v);
    }
    __syncthreads();
    if (tid < 64) {
        atomicAdd(&g_s3[tid],  (double)s3s[tid]);
        atomicAdd(&g_ss3[tid], (double)q3s[tid]);
    }
}

// ---------------- K_out: relu(bn3(z) + f) ----------------
__global__ void __launch_bounds__(256) k_out(const float* __restrict__ f,
                                             const float* __restrict__ g3,
                                             const float* __restrict__ b3,
                                             float* __restrict__ out) {
    __shared__ float sc[64], sh[64];
    int tid = threadIdx.x;
    if (tid < 64) {
        double cnt = (double)(Bb*Nn);
        double mu  = g_s3[tid] / cnt;
        double var = g_ss3[tid] / cnt - mu*mu;
        float s = g3[tid] * rsqrtf((float)var + EPSc);
        sc[tid] = s;
        sh[tid] = b3[tid] - (float)mu * s;
    }
    __syncthreads();
    int i = blockIdx.x * 256 + tid;
    int base = i * 4;
    int c = (base >> 11) & 63;
    float4 z  = *(const float4*)&g_z[base];
    float4 fv = *(const float4*)&f[base];
    float4 o;
    o.x = fmaxf(0.f, fmaf(z.x, sc[c], sh[c]) + fv.x);
    o.y = fmaxf(0.f, fmaf(z.y, sc[c], sh[c]) + fv.y);
    o.z = fmaxf(0.f, fmaf(z.z, sc[c], sh[c]) + fv.z);
    o.w = fmaxf(0.f, fmaf(z.w, sc[c], sh[c]) + fv.w);
    *(float4*)&out[base] = o;
}

// ---------------- launch ----------------
extern "C" void kernel_launch(void* const* d_in, const int* in_sizes, int n_in,
                              void* d_out, int out_size) {
    const float* p  = (const float*)d_in[0];
    const float* f  = (const float*)d_in[1];
    const float* w1 = (const float*)d_in[2];
    const float* g1 = (const float*)d_in[3];
    const float* b1 = (const float*)d_in[4];
    const float* w2 = (const float*)d_in[5];
    const float* g2 = (const float*)d_in[6];
    const float* b2 = (const float*)d_in[7];
    const float* w3 = (const float*)d_in[8];
    const float* g3 = (const float*)d_in[9];
    const float* b3 = (const float*)d_in[10];
    float* out = (float*)d_out;

    cudaFuncSetAttribute(k_mlp1, cudaFuncAttributeMaxDynamicSharedMemorySize, M1_SMEM);
    cudaFuncSetAttribute(k_mlp2, cudaFuncAttributeMaxDynamicSharedMemorySize, M2_SMEM);

    k_gfeat<<<512,  256>>>(f, w1, w2, w3);
    k_ballq<<<512, 1024>>>(p);
    k_agg  <<<2048, 256>>>(p, w1);
    k_mlp1 <<<512,  256, M1_SMEM>>>(g1, b1);
    k_mlp2 <<<256,  256, M2_SMEM>>>(g2, b2);
    k_out  <<<1024, 256>>>(f, g3, b3, out);
}